// round 1
// baseline (speedup 1.0000x reference)
#include <cuda_runtime.h>
#include <math.h>

// Problem constants
// B=4, S=2048, D=1024, H=16, HD=64
// M = B*S = 8192

// Scratch: __device__ globals (no allocation allowed)
__device__ float g_Q[4 * 16 * 2048 * 64];     // [B,H,S,HD]
__device__ float g_K[4 * 16 * 2048 * 64];
__device__ float g_V[4 * 16 * 2048 * 64];
__device__ float g_attn[4 * 2048 * 1024];     // merged [B,S,D]

// ---------------------------------------------------------------------------
// Tiled SGEMM: C[M,N] = A[M,K] @ B[K,N] + bias[N]
// 128x128 tile, BK=8, 256 threads, 8x8 microtile.
// SPLIT=true: scatter columns into g_Q/g_K/g_V with head-split layout.
// ---------------------------------------------------------------------------
template <bool SPLIT>
__global__ __launch_bounds__(256)
void sgemm_kernel(const float* __restrict__ A, const float* __restrict__ Bm,
                  const float* __restrict__ bias, float* __restrict__ C,
                  int M, int N, int K)
{
    __shared__ float As[8][128];   // transposed A tile
    __shared__ float Bs[8][128];

    const int tid = threadIdx.x;
    const int rowBase = blockIdx.y * 128;
    const int colBase = blockIdx.x * 128;

    const int aRow = tid >> 1;          // 0..127
    const int aCol = (tid & 1) * 4;     // 0 or 4
    const int bRow = tid >> 5;          // 0..7
    const int bCol = (tid & 31) * 4;    // 0..124

    const int ty = tid >> 4;            // 0..15 -> row group
    const int tx = tid & 15;            // 0..15 -> col group

    float acc[8][8];
#pragma unroll
    for (int i = 0; i < 8; i++)
#pragma unroll
        for (int j = 0; j < 8; j++) acc[i][j] = 0.0f;

    for (int k0 = 0; k0 < K; k0 += 8) {
        // Load A tile (transposed into As)
        float4 av = *(const float4*)(A + (size_t)(rowBase + aRow) * K + k0 + aCol);
        As[aCol + 0][aRow] = av.x;
        As[aCol + 1][aRow] = av.y;
        As[aCol + 2][aRow] = av.z;
        As[aCol + 3][aRow] = av.w;
        // Load B tile
        float4 bv = *(const float4*)(Bm + (size_t)(k0 + bRow) * N + colBase + bCol);
        *(float4*)&Bs[bRow][bCol] = bv;
        __syncthreads();

#pragma unroll
        for (int kk = 0; kk < 8; kk++) {
            float ar[8], br[8];
            *(float4*)&ar[0] = *(const float4*)&As[kk][ty * 8];
            *(float4*)&ar[4] = *(const float4*)&As[kk][ty * 8 + 4];
            *(float4*)&br[0] = *(const float4*)&Bs[kk][tx * 8];
            *(float4*)&br[4] = *(const float4*)&Bs[kk][tx * 8 + 4];
#pragma unroll
            for (int i = 0; i < 8; i++)
#pragma unroll
                for (int j = 0; j < 8; j++)
                    acc[i][j] = fmaf(ar[i], br[j], acc[i][j]);
        }
        __syncthreads();
    }

    // Epilogue
#pragma unroll
    for (int i = 0; i < 8; i++) {
        const int m = rowBase + ty * 8 + i;
#pragma unroll
        for (int j = 0; j < 8; j += 4) {
            const int n = colBase + tx * 8 + j;
            float4 v;
            v.x = acc[i][j + 0] + bias[n + 0];
            v.y = acc[i][j + 1] + bias[n + 1];
            v.z = acc[i][j + 2] + bias[n + 2];
            v.w = acc[i][j + 3] + bias[n + 3];
            if (SPLIT) {
                // n in [0,3072): part = q/k/v, then head-split
                const int part = n >> 10;
                const int dcol = n & 1023;
                const int h  = dcol >> 6;
                const int hd = dcol & 63;
                const int b  = m >> 11;
                const int s  = m & 2047;
                float* dst = (part == 0) ? g_Q : (part == 1) ? g_K : g_V;
                *(float4*)(dst + ((((size_t)b * 16 + h) * 2048 + s) * 64 + hd)) = v;
            } else {
                *(float4*)(C + (size_t)m * N + n) = v;
            }
        }
    }
}

// ---------------------------------------------------------------------------
// Flash attention (causal), fp32. One block = 64 query rows of one (b,h).
// BM=BN=HD=64, 256 threads, 4x4 microtile on the 64x64 score tile.
// Writes output directly in merged [B,S,H*HD] layout.
// ---------------------------------------------------------------------------
#define FLASH_SMEM_FLOATS (64*65 + 64*65 + 64*64 + 64*64)

__global__ __launch_bounds__(256)
void flash_kernel(float* __restrict__ Out)
{
    extern __shared__ float sm[];
    float* Qs = sm;                  // [64][65]
    float* Ks = sm + 64 * 65;        // [64][65]
    float* Vs = Ks + 64 * 65;        // [64][64]
    float* Ps = Vs + 64 * 64;        // [64][64]

    const int qb = blockIdx.x;       // 0..31
    const int bh = blockIdx.y;       // 0..63
    const int b = bh >> 4, h = bh & 15;

    const float* Qg = g_Q + ((size_t)bh * 2048 + qb * 64) * 64;
    const float* Kg = g_K + (size_t)bh * 2048 * 64;
    const float* Vg = g_V + (size_t)bh * 2048 * 64;

    const int tid = threadIdx.x;
    const int ty = tid >> 4;         // 0..15 : rows ty*4 .. ty*4+3
    const int tx = tid & 15;         // 0..15 : cols tx*4 .. tx*4+3

    // Load Q tile, pre-scaled by 1/sqrt(HD) = 0.125
#pragma unroll
    for (int t = 0; t < 4; t++) {
        int f = tid + t * 256;       // float4 index 0..1023
        int r = f >> 4, c = (f & 15) * 4;
        float4 v = *(const float4*)(Qg + r * 64 + c);
        Qs[r * 65 + c + 0] = v.x * 0.125f;
        Qs[r * 65 + c + 1] = v.y * 0.125f;
        Qs[r * 65 + c + 2] = v.z * 0.125f;
        Qs[r * 65 + c + 3] = v.w * 0.125f;
    }

    float m_i[4], l_i[4], o[4][4];
#pragma unroll
    for (int i = 0; i < 4; i++) {
        m_i[i] = -1e30f; l_i[i] = 0.0f;
#pragma unroll
        for (int c = 0; c < 4; c++) o[i][c] = 0.0f;
    }

    for (int kb = 0; kb <= qb; kb++) {
        // Load K, V tiles
#pragma unroll
        for (int t = 0; t < 4; t++) {
            int f = tid + t * 256;
            int r = f >> 4, c = (f & 15) * 4;
            float4 kv = *(const float4*)(Kg + (size_t)kb * 4096 + r * 64 + c);
            Ks[r * 65 + c + 0] = kv.x;
            Ks[r * 65 + c + 1] = kv.y;
            Ks[r * 65 + c + 2] = kv.z;
            Ks[r * 65 + c + 3] = kv.w;
            float4 vv = *(const float4*)(Vg + (size_t)kb * 4096 + r * 64 + c);
            *(float4*)&Vs[r * 64 + c] = vv;
        }
        __syncthreads();

        // S = Q @ K^T (scaled)
        float s_acc[4][4];
#pragma unroll
        for (int i = 0; i < 4; i++)
#pragma unroll
            for (int j = 0; j < 4; j++) s_acc[i][j] = 0.0f;

#pragma unroll 4
        for (int d = 0; d < 64; d++) {
            float qv[4], kv[4];
#pragma unroll
            for (int i = 0; i < 4; i++) qv[i] = Qs[(ty * 4 + i) * 65 + d];
#pragma unroll
            for (int j = 0; j < 4; j++) kv[j] = Ks[(tx * 4 + j) * 65 + d];
#pragma unroll
            for (int i = 0; i < 4; i++)
#pragma unroll
                for (int j = 0; j < 4; j++)
                    s_acc[i][j] = fmaf(qv[i], kv[j], s_acc[i][j]);
        }

        // Causal mask on the diagonal block
        if (kb == qb) {
#pragma unroll
            for (int i = 0; i < 4; i++)
#pragma unroll
                for (int j = 0; j < 4; j++)
                    if (tx * 4 + j > ty * 4 + i) s_acc[i][j] = -1e30f;
        }

        // Online softmax update (row groups = 16 lanes, within half-warp)
        float alpha[4];
#pragma unroll
        for (int i = 0; i < 4; i++) {
            float mx = fmaxf(fmaxf(s_acc[i][0], s_acc[i][1]),
                             fmaxf(s_acc[i][2], s_acc[i][3]));
#pragma unroll
            for (int off = 1; off < 16; off <<= 1)
                mx = fmaxf(mx, __shfl_xor_sync(0xffffffffu, mx, off));
            float m_new = fmaxf(m_i[i], mx);
            alpha[i] = __expf(m_i[i] - m_new);
            m_i[i] = m_new;
            float rsum = 0.0f;
#pragma unroll
            for (int j = 0; j < 4; j++) {
                float p = __expf(s_acc[i][j] - m_new);
                s_acc[i][j] = p;
                rsum += p;
            }
#pragma unroll
            for (int off = 1; off < 16; off <<= 1)
                rsum += __shfl_xor_sync(0xffffffffu, rsum, off);
            l_i[i] = l_i[i] * alpha[i] + rsum;
        }

        // Write P to smem
#pragma unroll
        for (int i = 0; i < 4; i++) {
            float4 pv = make_float4(s_acc[i][0], s_acc[i][1], s_acc[i][2], s_acc[i][3]);
            *(float4*)&Ps[(ty * 4 + i) * 64 + tx * 4] = pv;
        }
        __syncthreads();

        // O = O*alpha + P @ V
#pragma unroll
        for (int i = 0; i < 4; i++)
#pragma unroll
            for (int c = 0; c < 4; c++) o[i][c] *= alpha[i];

#pragma unroll 4
        for (int j = 0; j < 64; j++) {
            float4 vv = *(const float4*)&Vs[j * 64 + tx * 4];
            float pr[4];
#pragma unroll
            for (int i = 0; i < 4; i++) pr[i] = Ps[(ty * 4 + i) * 64 + j];
#pragma unroll
            for (int i = 0; i < 4; i++) {
                o[i][0] = fmaf(pr[i], vv.x, o[i][0]);
                o[i][1] = fmaf(pr[i], vv.y, o[i][1]);
                o[i][2] = fmaf(pr[i], vv.z, o[i][2]);
                o[i][3] = fmaf(pr[i], vv.w, o[i][3]);
            }
        }
        __syncthreads();
    }

    // Normalize and write to merged [B,S,D] layout
#pragma unroll
    for (int i = 0; i < 4; i++) {
        float inv = 1.0f / l_i[i];
        int qrow = qb * 64 + ty * 4 + i;
        float4 v = make_float4(o[i][0] * inv, o[i][1] * inv, o[i][2] * inv, o[i][3] * inv);
        *(float4*)(Out + ((size_t)b * 2048 + qrow) * 1024 + h * 64 + tx * 4) = v;
    }
}

// ---------------------------------------------------------------------------
extern "C" void kernel_launch(void* const* d_in, const int* in_sizes, int n_in,
                              void* d_out, int out_size)
{
    const float* x     = (const float*)d_in[0];   // [4,2048,1024]
    const float* W_qkv = (const float*)d_in[1];   // [1024,3072]
    const float* b_qkv = (const float*)d_in[2];   // [3072]
    const float* W_out = (const float*)d_in[3];   // [1024,1024]
    const float* b_out = (const float*)d_in[4];   // [1024]
    float* out = (float*)d_out;                   // [4,2048,1024]

    float* attn = nullptr;
    cudaGetSymbolAddress((void**)&attn, g_attn);

    const int M = 8192;
    dim3 blk(256);

    // 1) QKV projection with fused bias + head-split scatter
    sgemm_kernel<true><<<dim3(3072 / 128, M / 128), blk>>>(
        x, W_qkv, b_qkv, nullptr, M, 3072, 1024);

    // 2) Causal flash attention
    const int smem_bytes = FLASH_SMEM_FLOATS * (int)sizeof(float);
    cudaFuncSetAttribute(flash_kernel,
                         cudaFuncAttributeMaxDynamicSharedMemorySize, smem_bytes);
    flash_kernel<<<dim3(32, 64), blk, smem_bytes>>>(attn);

    // 3) Output projection
    sgemm_kernel<false><<<dim3(1024 / 128, M / 128), blk>>>(
        attn, W_out, b_out, out, M, 1024, 1024);
}

// round 2
// speedup vs baseline: 2.3845x; 2.3845x over previous
#include <cuda_runtime.h>
#include <math.h>

// B=4, S=2048, D=1024, H=16, HD=64, M=B*S=8192
#define SCALE_LOG2E 0.18033688011112042f   // (1/8) * log2(e)

// Scratch (no allocation allowed)
__device__ float g_Q[4 * 16 * 2048 * 64];     // [B,H,S,HD]
__device__ float g_K[4 * 16 * 2048 * 64];
__device__ float g_V[4 * 16 * 2048 * 64];
__device__ float g_attn[4 * 2048 * 1024];     // merged [B,S,D]

__device__ __forceinline__ unsigned f2tf32(float f) {
    unsigned r;
    asm("cvt.rna.tf32.f32 %0, %1;" : "=r"(r) : "f"(f));
    return r;
}

__device__ __forceinline__ void mma_tf32(float* d, const unsigned* a, const unsigned* b) {
    asm volatile(
        "mma.sync.aligned.m16n8k8.row.col.f32.tf32.tf32.f32 "
        "{%0,%1,%2,%3}, {%4,%5,%6,%7}, {%8,%9}, {%0,%1,%2,%3};"
        : "+f"(d[0]), "+f"(d[1]), "+f"(d[2]), "+f"(d[3])
        : "r"(a[0]), "r"(a[1]), "r"(a[2]), "r"(a[3]), "r"(b[0]), "r"(b[1]));
}

// ---------------------------------------------------------------------------
// TF32 MMA GEMM: C[M,N] = A[M,K] @ B[K,N] + bias
// 128x128 block, BK=16, 256 threads (8 warps 2x4), warp tile 64x32.
// Double-buffered smem. Strides chosen for conflict-free LDS/STS.
// ---------------------------------------------------------------------------
template <bool SPLIT>
__global__ __launch_bounds__(256, 2)
void mma_gemm(const float* __restrict__ A, const float* __restrict__ Bm,
              const float* __restrict__ bias, float* __restrict__ C,
              int M, int N, int K)
{
    __shared__ unsigned As[2][16][136];   // [k][m], stride 136 (8 mod 32)
    __shared__ unsigned Bs[2][16][136];   // [k][n]

    const int tid  = threadIdx.x;
    const int lane = tid & 31;
    const int warp = tid >> 5;
    const int gid  = lane >> 2, tg = lane & 3;
    const int wm   = warp >> 2, wn = warp & 3;      // 2x4 warps
    const int rowBase = blockIdx.y * 128;
    const int colBase = blockIdx.x * 128;

    // loaders
    const int arow = tid & 63;        // A rows arow, arow+64
    const int ak4  = tid >> 6;        // A k-group (k = ak4*4..+3)
    const int bk   = tid >> 5;        // B k rows bk, bk+8
    const int bn4  = lane;            // B col group (n = bn4*4)

    float acc[4][4][4];
#pragma unroll
    for (int mt = 0; mt < 4; mt++)
#pragma unroll
        for (int nt = 0; nt < 4; nt++)
#pragma unroll
            for (int r = 0; r < 4; r++) acc[mt][nt][r] = 0.0f;

    float4 ra0, ra1, rb0, rb1;

    auto gload = [&](int k0) {
        ra0 = *(const float4*)(A + (size_t)(rowBase + arow) * K + k0 + ak4 * 4);
        ra1 = *(const float4*)(A + (size_t)(rowBase + arow + 64) * K + k0 + ak4 * 4);
        rb0 = *(const float4*)(Bm + (size_t)(k0 + bk) * N + colBase + bn4 * 4);
        rb1 = *(const float4*)(Bm + (size_t)(k0 + bk + 8) * N + colBase + bn4 * 4);
    };
    auto sstore = [&](int buf) {
        As[buf][ak4 * 4 + 0][arow] = f2tf32(ra0.x);
        As[buf][ak4 * 4 + 1][arow] = f2tf32(ra0.y);
        As[buf][ak4 * 4 + 2][arow] = f2tf32(ra0.z);
        As[buf][ak4 * 4 + 3][arow] = f2tf32(ra0.w);
        As[buf][ak4 * 4 + 0][arow + 64] = f2tf32(ra1.x);
        As[buf][ak4 * 4 + 1][arow + 64] = f2tf32(ra1.y);
        As[buf][ak4 * 4 + 2][arow + 64] = f2tf32(ra1.z);
        As[buf][ak4 * 4 + 3][arow + 64] = f2tf32(ra1.w);
        uint4 u0 = make_uint4(f2tf32(rb0.x), f2tf32(rb0.y), f2tf32(rb0.z), f2tf32(rb0.w));
        uint4 u1 = make_uint4(f2tf32(rb1.x), f2tf32(rb1.y), f2tf32(rb1.z), f2tf32(rb1.w));
        *(uint4*)&Bs[buf][bk][bn4 * 4]     = u0;
        *(uint4*)&Bs[buf][bk + 8][bn4 * 4] = u1;
    };
    auto compute = [&](int buf) {
#pragma unroll
        for (int ks = 0; ks < 2; ks++) {
            unsigned af[4][4];
#pragma unroll
            for (int mt = 0; mt < 4; mt++) {
                int r0 = wm * 64 + mt * 16 + gid;
                af[mt][0] = As[buf][ks * 8 + tg][r0];
                af[mt][1] = As[buf][ks * 8 + tg][r0 + 8];
                af[mt][2] = As[buf][ks * 8 + tg + 4][r0];
                af[mt][3] = As[buf][ks * 8 + tg + 4][r0 + 8];
            }
            unsigned bf[4][2];
#pragma unroll
            for (int nt = 0; nt < 4; nt++) {
                int c0 = wn * 32 + nt * 8 + gid;
                bf[nt][0] = Bs[buf][ks * 8 + tg][c0];
                bf[nt][1] = Bs[buf][ks * 8 + tg + 4][c0];
            }
#pragma unroll
            for (int mt = 0; mt < 4; mt++)
#pragma unroll
                for (int nt = 0; nt < 4; nt++)
                    mma_tf32(acc[mt][nt], af[mt], bf[nt]);
        }
    };

    gload(0);
    sstore(0);
    __syncthreads();
    const int nsteps = K >> 4;
    for (int s = 0; s < nsteps; s++) {
        int buf = s & 1;
        if (s + 1 < nsteps) gload((s + 1) * 16);
        compute(buf);
        if (s + 1 < nsteps) sstore(buf ^ 1);
        __syncthreads();
    }

    // Epilogue
#pragma unroll
    for (int mt = 0; mt < 4; mt++) {
        int m = rowBase + wm * 64 + mt * 16 + gid;
#pragma unroll
        for (int nt = 0; nt < 4; nt++) {
            int n = colBase + wn * 32 + nt * 8 + 2 * tg;
            float2 v0 = make_float2(acc[mt][nt][0] + bias[n], acc[mt][nt][1] + bias[n + 1]);
            float2 v1 = make_float2(acc[mt][nt][2] + bias[n], acc[mt][nt][3] + bias[n + 1]);
            if (SPLIT) {
                const int part = n >> 10;
                const int dcol = n & 1023;
                const int hh = dcol >> 6, hd = dcol & 63;
                float* dst = (part == 0) ? g_Q : (part == 1) ? g_K : g_V;
                {
                    int bb = m >> 11, si = m & 2047;
                    *(float2*)(dst + ((((size_t)bb * 16 + hh) * 2048 + si) * 64 + hd)) = v0;
                }
                {
                    int m2 = m + 8;
                    int bb = m2 >> 11, si = m2 & 2047;
                    *(float2*)(dst + ((((size_t)bb * 16 + hh) * 2048 + si) * 64 + hd)) = v1;
                }
            } else {
                *(float2*)(C + (size_t)m * N + n) = v0;
                *(float2*)(C + (size_t)(m + 8) * N + n) = v1;
            }
        }
    }
}

// ---------------------------------------------------------------------------
// Causal flash attention, TF32 mma. BM=128, BN=64, 256 threads (8 warps),
// each warp owns 16 query rows x 64 keys / 64 dims.
// ---------------------------------------------------------------------------
#define FLASH_SMEM_BYTES ((128 * 68 + 64 * 68 + 64 * 72 + 128 * 68) * 4)

__global__ __launch_bounds__(256, 1)
void flash_mma(float* __restrict__ Out)
{
    extern __shared__ unsigned sm[];
    unsigned (*Qs)[68] = (unsigned(*)[68])sm;                                   // [qrow][d]
    unsigned (*Ks)[68] = (unsigned(*)[68])(sm + 128 * 68);                      // [key][d]
    unsigned (*Vs)[72] = (unsigned(*)[72])(sm + 128 * 68 + 64 * 68);            // [key][d]
    unsigned (*Ps)[68] = (unsigned(*)[68])(sm + 128 * 68 + 64 * 68 + 64 * 72);  // [qrow][key]

    const int qb = blockIdx.x;        // 0..15
    const int bh = blockIdx.y;        // 0..63
    const int b = bh >> 4, h = bh & 15;
    const int tid = threadIdx.x, lane = tid & 31, w = tid >> 5;
    const int gid = lane >> 2, tg = lane & 3;

    const float* Qg = g_Q + ((size_t)bh * 2048 + qb * 128) * 64;
    const float* Kg = g_K + (size_t)bh * 2048 * 64;
    const float* Vg = g_V + (size_t)bh * 2048 * 64;

    // Load Q (pre-scaled into exp2 domain), convert to tf32
#pragma unroll
    for (int j = 0; j < 8; j++) {
        int f = tid + 256 * j;
        int r = f >> 4, c4 = (f & 15) * 4;
        float4 v = *(const float4*)(Qg + r * 64 + c4);
        uint4 u = make_uint4(f2tf32(v.x * SCALE_LOG2E), f2tf32(v.y * SCALE_LOG2E),
                             f2tf32(v.z * SCALE_LOG2E), f2tf32(v.w * SCALE_LOG2E));
        *(uint4*)&Qs[r][c4] = u;
    }

    float m0 = -1e30f, m1 = -1e30f, l0 = 0.0f, l1 = 0.0f;
    float o[8][4];
#pragma unroll
    for (int nt = 0; nt < 8; nt++)
#pragma unroll
        for (int r = 0; r < 4; r++) o[nt][r] = 0.0f;

    const int ktmax = 2 * qb + 1;
    for (int kt = 0; kt <= ktmax; kt++) {
        // Load K/V tiles
#pragma unroll
        for (int j = 0; j < 4; j++) {
            int f = tid + 256 * j;
            int r = f >> 4, c4 = (f & 15) * 4;
            float4 kv = *(const float4*)(Kg + ((size_t)kt * 64 + r) * 64 + c4);
            *(uint4*)&Ks[r][c4] = make_uint4(f2tf32(kv.x), f2tf32(kv.y), f2tf32(kv.z), f2tf32(kv.w));
            float4 vv = *(const float4*)(Vg + ((size_t)kt * 64 + r) * 64 + c4);
            *(uint4*)&Vs[r][c4] = make_uint4(f2tf32(vv.x), f2tf32(vv.y), f2tf32(vv.z), f2tf32(vv.w));
        }
        __syncthreads();

        // S = Q @ K^T
        float sacc[8][4];
#pragma unroll
        for (int nt = 0; nt < 8; nt++)
#pragma unroll
            for (int r = 0; r < 4; r++) sacc[nt][r] = 0.0f;

#pragma unroll
        for (int ks = 0; ks < 8; ks++) {
            unsigned af[4];
            af[0] = Qs[w * 16 + gid][ks * 8 + tg];
            af[1] = Qs[w * 16 + gid + 8][ks * 8 + tg];
            af[2] = Qs[w * 16 + gid][ks * 8 + tg + 4];
            af[3] = Qs[w * 16 + gid + 8][ks * 8 + tg + 4];
#pragma unroll
            for (int nt = 0; nt < 8; nt++) {
                unsigned bf[2];
                bf[0] = Ks[nt * 8 + gid][ks * 8 + tg];
                bf[1] = Ks[nt * 8 + gid][ks * 8 + tg + 4];
                mma_tf32(sacc[nt], af, bf);
            }
        }

        // Causal mask (only possibly-diagonal tiles)
        if (kt >= 2 * qb) {
            int r0 = qb * 128 + w * 16 + gid;
            int r1 = r0 + 8;
#pragma unroll
            for (int nt = 0; nt < 8; nt++) {
                int c = kt * 64 + nt * 8 + 2 * tg;
                if (c > r0)     sacc[nt][0] = -1e30f;
                if (c + 1 > r0) sacc[nt][1] = -1e30f;
                if (c > r1)     sacc[nt][2] = -1e30f;
                if (c + 1 > r1) sacc[nt][3] = -1e30f;
            }
        }

        // Online softmax (exp2 domain); rows owned by quads (lanes gid*4+tg)
        float mx0 = -1e30f, mx1 = -1e30f;
#pragma unroll
        for (int nt = 0; nt < 8; nt++) {
            mx0 = fmaxf(mx0, fmaxf(sacc[nt][0], sacc[nt][1]));
            mx1 = fmaxf(mx1, fmaxf(sacc[nt][2], sacc[nt][3]));
        }
        mx0 = fmaxf(mx0, __shfl_xor_sync(0xffffffffu, mx0, 1));
        mx0 = fmaxf(mx0, __shfl_xor_sync(0xffffffffu, mx0, 2));
        mx1 = fmaxf(mx1, __shfl_xor_sync(0xffffffffu, mx1, 1));
        mx1 = fmaxf(mx1, __shfl_xor_sync(0xffffffffu, mx1, 2));
        float mn0 = fmaxf(m0, mx0), mn1 = fmaxf(m1, mx1);
        float a0 = exp2f(m0 - mn0), a1 = exp2f(m1 - mn1);
        m0 = mn0; m1 = mn1;
        float rs0 = 0.0f, rs1 = 0.0f;
#pragma unroll
        for (int nt = 0; nt < 8; nt++) {
            sacc[nt][0] = exp2f(sacc[nt][0] - mn0); rs0 += sacc[nt][0];
            sacc[nt][1] = exp2f(sacc[nt][1] - mn0); rs0 += sacc[nt][1];
            sacc[nt][2] = exp2f(sacc[nt][2] - mn1); rs1 += sacc[nt][2];
            sacc[nt][3] = exp2f(sacc[nt][3] - mn1); rs1 += sacc[nt][3];
        }
        rs0 += __shfl_xor_sync(0xffffffffu, rs0, 1);
        rs0 += __shfl_xor_sync(0xffffffffu, rs0, 2);
        rs1 += __shfl_xor_sync(0xffffffffu, rs1, 1);
        rs1 += __shfl_xor_sync(0xffffffffu, rs1, 2);
        l0 = l0 * a0 + rs0;
        l1 = l1 * a1 + rs1;
#pragma unroll
        for (int nt = 0; nt < 8; nt++) {
            o[nt][0] *= a0; o[nt][1] *= a0; o[nt][2] *= a1; o[nt][3] *= a1;
        }

        // Store P (tf32) for PV mma
#pragma unroll
        for (int nt = 0; nt < 8; nt++) {
            *(uint2*)&Ps[w * 16 + gid][nt * 8 + 2 * tg] =
                make_uint2(f2tf32(sacc[nt][0]), f2tf32(sacc[nt][1]));
            *(uint2*)&Ps[w * 16 + gid + 8][nt * 8 + 2 * tg] =
                make_uint2(f2tf32(sacc[nt][2]), f2tf32(sacc[nt][3]));
        }
        __syncthreads();

        // O += P @ V
#pragma unroll
        for (int ks = 0; ks < 8; ks++) {
            unsigned af[4];
            af[0] = Ps[w * 16 + gid][ks * 8 + tg];
            af[1] = Ps[w * 16 + gid + 8][ks * 8 + tg];
            af[2] = Ps[w * 16 + gid][ks * 8 + tg + 4];
            af[3] = Ps[w * 16 + gid + 8][ks * 8 + tg + 4];
#pragma unroll
            for (int nt = 0; nt < 8; nt++) {
                unsigned bf[2];
                bf[0] = Vs[ks * 8 + tg][nt * 8 + gid];
                bf[1] = Vs[ks * 8 + tg + 4][nt * 8 + gid];
                mma_tf32(o[nt], af, bf);
            }
        }
        __syncthreads();
    }

    // Normalize + write merged [B,S,D]
    float i0 = 1.0f / l0, i1 = 1.0f / l1;
    int r0 = qb * 128 + w * 16 + gid;
    float* p0 = Out + ((size_t)b * 2048 + r0) * 1024 + h * 64;
    float* p1 = p0 + (size_t)8 * 1024;
#pragma unroll
    for (int nt = 0; nt < 8; nt++) {
        *(float2*)(p0 + nt * 8 + 2 * tg) = make_float2(o[nt][0] * i0, o[nt][1] * i0);
        *(float2*)(p1 + nt * 8 + 2 * tg) = make_float2(o[nt][2] * i1, o[nt][3] * i1);
    }
}

// ---------------------------------------------------------------------------
extern "C" void kernel_launch(void* const* d_in, const int* in_sizes, int n_in,
                              void* d_out, int out_size)
{
    const float* x     = (const float*)d_in[0];
    const float* W_qkv = (const float*)d_in[1];
    const float* b_qkv = (const float*)d_in[2];
    const float* W_out = (const float*)d_in[3];
    const float* b_out = (const float*)d_in[4];
    float* out = (float*)d_out;

    float* attn = nullptr;
    cudaGetSymbolAddress((void**)&attn, g_attn);

    // 1) QKV projection (fused bias + head-split scatter)
    mma_gemm<true><<<dim3(24, 64), 256>>>(x, W_qkv, b_qkv, nullptr, 8192, 3072, 1024);

    // 2) Causal flash attention
    cudaFuncSetAttribute(flash_mma, cudaFuncAttributeMaxDynamicSharedMemorySize,
                         FLASH_SMEM_BYTES);
    flash_mma<<<dim3(16, 64), 256, FLASH_SMEM_BYTES>>>(attn);

    // 3) Output projection
    mma_gemm<false><<<dim3(8, 64), 256>>>(attn, W_out, b_out, out, 8192, 1024, 1024);
}

// round 6
// speedup vs baseline: 2.9710x; 1.2460x over previous
#include <cuda_runtime.h>
#include <cstdint>
#include <math.h>

// B=4, S=2048, D=1024, H=16, HD=64, M=8192
#define SCALE_LOG2E 0.18033688011112042f   // (1/8) * log2(e)

// ---------------- scratch (no allocation allowed) ----------------
__device__ float g_Q[4 * 16 * 2048 * 64];     // [B,H,S,HD] tf32-rounded
__device__ float g_K[4 * 16 * 2048 * 64];
__device__ float g_V[4 * 16 * 2048 * 64];
__device__ float g_attn[4 * 2048 * 1024];     // merged [B,S,D], tf32-rounded
__device__ float g_xtf[8192 * 1024];          // x, tf32-rounded
__device__ float g_Wqkv_r[1024 * 3072];       // W_qkv, tf32-rounded (layout unchanged [K,N])
__device__ float g_Wout_r[1024 * 1024];       // W_out, tf32-rounded

// ---------------- helpers ----------------
__device__ __forceinline__ unsigned f2tf32(float f) {
    unsigned r; asm("cvt.rna.tf32.f32 %0, %1;" : "=r"(r) : "f"(f)); return r;
}
__device__ __forceinline__ uint32_t smem_u32(const void* p) {
    uint32_t a;
    asm("{ .reg .u64 t; cvta.to.shared.u64 t, %1; cvt.u32.u64 %0, t; }" : "=r"(a) : "l"(p));
    return a;
}
__device__ __forceinline__ void cp_async16(uint32_t dst, const void* src) {
    asm volatile("cp.async.cg.shared.global [%0], [%1], 16;" :: "r"(dst), "l"(src));
}
#define CP_COMMIT()  asm volatile("cp.async.commit_group;" ::: "memory")
#define CP_WAIT(n)   asm volatile("cp.async.wait_group %0;" :: "n"(n) : "memory")

__device__ __forceinline__ void mma_tf32(float* d, const unsigned* a, const unsigned* b) {
    asm volatile(
        "mma.sync.aligned.m16n8k8.row.col.f32.tf32.tf32.f32 "
        "{%0,%1,%2,%3}, {%4,%5,%6,%7}, {%8,%9}, {%0,%1,%2,%3};"
        : "+f"(d[0]), "+f"(d[1]), "+f"(d[2]), "+f"(d[3])
        : "r"(a[0]), "r"(a[1]), "r"(a[2]), "r"(a[3]), "r"(b[0]), "r"(b[1]));
}

// ---------------- prep: elementwise RNA rounding ----------------
__global__ void cvt_rna_kernel(const float4* __restrict__ in, float4* __restrict__ out) {
    int i = blockIdx.x * blockDim.x + threadIdx.x;
    float4 v = in[i];
    out[i] = make_float4(__uint_as_float(f2tf32(v.x)), __uint_as_float(f2tf32(v.y)),
                         __uint_as_float(f2tf32(v.z)), __uint_as_float(f2tf32(v.w)));
}

// ---------------- TF32 mma GEMM with cp.async pipeline ----------------
// C[M,N] = A[M,1024] @ B[1024,N] + bias.  A, B pre-rounded to tf32 values.
// 128x128 CTA tile, BK=16, 256 threads (warps 2x4, warp tile 64x32), 3 stages.
// As[m][k] stride 20 (conflict-free frag LDS), Bs[k][n] stride 136.
#define GK 1024
#define NSTEPS 64
#define AS_FLOATS (128 * 20)     // 2560
#define BS_FLOATS (16 * 136)     // 2176
#define STAGE_FLOATS (AS_FLOATS + BS_FLOATS)   // 4736
#define STAGE_BYTES (STAGE_FLOATS * 4)          // 18944
#define GEMM_SMEM (3 * STAGE_BYTES)             // 56832

template <bool SPLIT>
__global__ __launch_bounds__(256, 2)
void mma_gemm2(const float* __restrict__ A, const float* __restrict__ Bm,
               const float* __restrict__ bias, float* __restrict__ C, int N)
{
    extern __shared__ unsigned smu[];
    const uint32_t sbase = smem_u32(smu);

    const int tid  = threadIdx.x;
    const int lane = tid & 31;
    const int warp = tid >> 5;
    const int gid  = lane >> 2, tg = lane & 3;
    const int wm   = warp >> 2, wn = warp & 3;
    const int rowBase = blockIdx.y * 128;
    const int colBase = blockIdx.x * 128;

    // fill thread mapping
    const int am = tid >> 1;              // A row 0..127
    const int ac = tid & 1;               // A 16B chunk 0..1 (x2 iterations -> 4 chunks)
    const int bk = tid >> 5;              // B row 0..7 (+8)
    const int bc = lane;                  // B 16B chunk 0..31

    float acc[4][4][4];
#pragma unroll
    for (int mt = 0; mt < 4; mt++)
#pragma unroll
        for (int nt = 0; nt < 4; nt++)
#pragma unroll
            for (int r = 0; r < 4; r++) acc[mt][nt][r] = 0.0f;

    auto fill = [&](int s, int k0) {
        uint32_t sA = sbase + s * STAGE_BYTES;
        uint32_t sB = sA + AS_FLOATS * 4;
        // A: 128 rows x 16 floats; thread -> row am, chunks (ac, ac+2)
        const float* ap = A + (size_t)(rowBase + am) * GK + k0;
        cp_async16(sA + am * 80 + ac * 16,        ap + ac * 4);
        cp_async16(sA + am * 80 + (ac + 2) * 16,  ap + (ac + 2) * 4);
        // B: 16 rows x 128 floats; thread -> rows bk, bk+8, chunk bc
        const float* bp = Bm + (size_t)(k0 + bk) * N + colBase;
        cp_async16(sB + bk * 544 + bc * 16,       bp + bc * 4);
        cp_async16(sB + (bk + 8) * 544 + bc * 16, bp + (size_t)8 * N + bc * 4);
        CP_COMMIT();
    };

    auto compute = [&](int s) {
        const unsigned* As = smu + s * STAGE_FLOATS;
        const unsigned* Bs = As + AS_FLOATS;
#pragma unroll
        for (int ks = 0; ks < 2; ks++) {
            unsigned af[4][4];
#pragma unroll
            for (int mt = 0; mt < 4; mt++) {
                int r0 = (wm * 64 + mt * 16 + gid) * 20 + ks * 8 + tg;
                af[mt][0] = As[r0];
                af[mt][1] = As[r0 + 160];   // +8 rows
                af[mt][2] = As[r0 + 4];     // +4 k
                af[mt][3] = As[r0 + 164];
            }
            unsigned bf[4][2];
#pragma unroll
            for (int nt = 0; nt < 4; nt++) {
                int c0 = (ks * 8 + tg) * 136 + wn * 32 + nt * 8 + gid;
                bf[nt][0] = Bs[c0];
                bf[nt][1] = Bs[c0 + 544];   // +4 k rows
            }
#pragma unroll
            for (int mt = 0; mt < 4; mt++)
#pragma unroll
                for (int nt = 0; nt < 4; nt++)
                    mma_tf32(acc[mt][nt], af[mt], bf[nt]);
        }
    };

    fill(0, 0);
    fill(1, 16);

    int s = 0, sf = 2;
#pragma unroll 1
    for (int i = 0; i < NSTEPS; i++) {
        if (i == NSTEPS - 1) { CP_WAIT(0); } else { CP_WAIT(1); }
        __syncthreads();
        if (i + 2 < NSTEPS) {
            fill(sf, (i + 2) * 16);
            sf = (sf == 2) ? 0 : sf + 1;
        }
        compute(s);
        s = (s == 2) ? 0 : s + 1;
        __syncthreads();
    }

    // Epilogue
#pragma unroll
    for (int mt = 0; mt < 4; mt++) {
        int m = rowBase + wm * 64 + mt * 16 + gid;
#pragma unroll
        for (int nt = 0; nt < 4; nt++) {
            int n = colBase + wn * 32 + nt * 8 + 2 * tg;
            float2 bv = *(const float2*)(bias + n);
            float2 v0 = make_float2(acc[mt][nt][0] + bv.x, acc[mt][nt][1] + bv.y);
            float2 v1 = make_float2(acc[mt][nt][2] + bv.x, acc[mt][nt][3] + bv.y);
            if (SPLIT) {
                // round Q/K/V to tf32 values so flash consumes raw bits
                v0.x = __uint_as_float(f2tf32(v0.x)); v0.y = __uint_as_float(f2tf32(v0.y));
                v1.x = __uint_as_float(f2tf32(v1.x)); v1.y = __uint_as_float(f2tf32(v1.y));
                const int part = n >> 10, dcol = n & 1023;
                const int hh = dcol >> 6, hd = dcol & 63;
                float* dst = (part == 0) ? g_Q : (part == 1) ? g_K : g_V;
                {
                    int bb = m >> 11, si = m & 2047;
                    *(float2*)(dst + ((((size_t)bb * 16 + hh) * 2048 + si) * 64 + hd)) = v0;
                }
                {
                    int m2 = m + 8, bb = m2 >> 11, si = m2 & 2047;
                    *(float2*)(dst + ((((size_t)bb * 16 + hh) * 2048 + si) * 64 + hd)) = v1;
                }
            } else {
                *(float2*)(C + (size_t)m * N + n) = v0;
                *(float2*)(C + (size_t)(m + 8) * N + n) = v1;
            }
        }
    }
}

// ---------------- causal flash attention (tf32 mma.sync) ----------------
// BM=128, BN=64, 256 threads. K/V pre-rounded -> raw copies. Output rounded.
#define FLASH_SMEM_BYTES ((128 * 68 + 64 * 68 + 64 * 72 + 128 * 68) * 4)

__global__ __launch_bounds__(256, 1)
void flash_mma(float* __restrict__ Out)
{
    extern __shared__ unsigned sm[];
    unsigned (*Qs)[68] = (unsigned(*)[68])sm;
    unsigned (*Ks)[68] = (unsigned(*)[68])(sm + 128 * 68);
    unsigned (*Vs)[72] = (unsigned(*)[72])(sm + 128 * 68 + 64 * 68);
    unsigned (*Ps)[68] = (unsigned(*)[68])(sm + 128 * 68 + 64 * 68 + 64 * 72);

    const int qb = blockIdx.x;
    const int bh = blockIdx.y;
    const int b = bh >> 4, h = bh & 15;
    const int tid = threadIdx.x, lane = tid & 31, w = tid >> 5;
    const int gid = lane >> 2, tg = lane & 3;

    const float* Qg = g_Q + ((size_t)bh * 2048 + qb * 128) * 64;
    const float* Kg = g_K + (size_t)bh * 2048 * 64;
    const float* Vg = g_V + (size_t)bh * 2048 * 64;

    // Q: scale into exp2 domain, then RNA round (accuracy-critical)
#pragma unroll
    for (int j = 0; j < 8; j++) {
        int f = tid + 256 * j;
        int r = f >> 4, c4 = (f & 15) * 4;
        float4 v = *(const float4*)(Qg + r * 64 + c4);
        uint4 u = make_uint4(f2tf32(v.x * SCALE_LOG2E), f2tf32(v.y * SCALE_LOG2E),
                             f2tf32(v.z * SCALE_LOG2E), f2tf32(v.w * SCALE_LOG2E));
        *(uint4*)&Qs[r][c4] = u;
    }

    float m0 = -1e30f, m1 = -1e30f, l0 = 0.0f, l1 = 0.0f;
    float o[8][4];
#pragma unroll
    for (int nt = 0; nt < 8; nt++)
#pragma unroll
        for (int r = 0; r < 4; r++) o[nt][r] = 0.0f;

    const int ktmax = 2 * qb + 1;
    for (int kt = 0; kt <= ktmax; kt++) {
        // K/V already tf32 values: raw bit copies
#pragma unroll
        for (int j = 0; j < 4; j++) {
            int f = tid + 256 * j;
            int r = f >> 4, c4 = (f & 15) * 4;
            uint4 kv = *(const uint4*)(Kg + ((size_t)kt * 64 + r) * 64 + c4);
            *(uint4*)&Ks[r][c4] = kv;
            uint4 vv = *(const uint4*)(Vg + ((size_t)kt * 64 + r) * 64 + c4);
            *(uint4*)&Vs[r][c4] = vv;
        }
        __syncthreads();

        float sacc[8][4];
#pragma unroll
        for (int nt = 0; nt < 8; nt++)
#pragma unroll
            for (int r = 0; r < 4; r++) sacc[nt][r] = 0.0f;

#pragma unroll
        for (int ks = 0; ks < 8; ks++) {
            unsigned af[4];
            af[0] = Qs[w * 16 + gid][ks * 8 + tg];
            af[1] = Qs[w * 16 + gid + 8][ks * 8 + tg];
            af[2] = Qs[w * 16 + gid][ks * 8 + tg + 4];
            af[3] = Qs[w * 16 + gid + 8][ks * 8 + tg + 4];
#pragma unroll
            for (int nt = 0; nt < 8; nt++) {
                unsigned bf[2];
                bf[0] = Ks[nt * 8 + gid][ks * 8 + tg];
                bf[1] = Ks[nt * 8 + gid][ks * 8 + tg + 4];
                mma_tf32(sacc[nt], af, bf);
            }
        }

        if (kt >= 2 * qb) {
            int r0 = qb * 128 + w * 16 + gid;
            int r1 = r0 + 8;
#pragma unroll
            for (int nt = 0; nt < 8; nt++) {
                int c = kt * 64 + nt * 8 + 2 * tg;
                if (c > r0)     sacc[nt][0] = -1e30f;
                if (c + 1 > r0) sacc[nt][1] = -1e30f;
                if (c > r1)     sacc[nt][2] = -1e30f;
                if (c + 1 > r1) sacc[nt][3] = -1e30f;
            }
        }

        float mx0 = -1e30f, mx1 = -1e30f;
#pragma unroll
        for (int nt = 0; nt < 8; nt++) {
            mx0 = fmaxf(mx0, fmaxf(sacc[nt][0], sacc[nt][1]));
            mx1 = fmaxf(mx1, fmaxf(sacc[nt][2], sacc[nt][3]));
        }
        mx0 = fmaxf(mx0, __shfl_xor_sync(0xffffffffu, mx0, 1));
        mx0 = fmaxf(mx0, __shfl_xor_sync(0xffffffffu, mx0, 2));
        mx1 = fmaxf(mx1, __shfl_xor_sync(0xffffffffu, mx1, 1));
        mx1 = fmaxf(mx1, __shfl_xor_sync(0xffffffffu, mx1, 2));
        float mn0 = fmaxf(m0, mx0), mn1 = fmaxf(m1, mx1);
        float a0 = exp2f(m0 - mn0), a1 = exp2f(m1 - mn1);
        m0 = mn0; m1 = mn1;
        float rs0 = 0.0f, rs1 = 0.0f;
#pragma unroll
        for (int nt = 0; nt < 8; nt++) {
            sacc[nt][0] = exp2f(sacc[nt][0] - mn0); rs0 += sacc[nt][0];
            sacc[nt][1] = exp2f(sacc[nt][1] - mn0); rs0 += sacc[nt][1];
            sacc[nt][2] = exp2f(sacc[nt][2] - mn1); rs1 += sacc[nt][2];
            sacc[nt][3] = exp2f(sacc[nt][3] - mn1); rs1 += sacc[nt][3];
        }
        rs0 += __shfl_xor_sync(0xffffffffu, rs0, 1);
        rs0 += __shfl_xor_sync(0xffffffffu, rs0, 2);
        rs1 += __shfl_xor_sync(0xffffffffu, rs1, 1);
        rs1 += __shfl_xor_sync(0xffffffffu, rs1, 2);
        l0 = l0 * a0 + rs0;
        l1 = l1 * a1 + rs1;
#pragma unroll
        for (int nt = 0; nt < 8; nt++) {
            o[nt][0] *= a0; o[nt][1] *= a0; o[nt][2] *= a1; o[nt][3] *= a1;
        }

#pragma unroll
        for (int nt = 0; nt < 8; nt++) {
            *(uint2*)&Ps[w * 16 + gid][nt * 8 + 2 * tg] =
                make_uint2(f2tf32(sacc[nt][0]), f2tf32(sacc[nt][1]));
            *(uint2*)&Ps[w * 16 + gid + 8][nt * 8 + 2 * tg] =
                make_uint2(f2tf32(sacc[nt][2]), f2tf32(sacc[nt][3]));
        }
        __syncthreads();

#pragma unroll
        for (int ks = 0; ks < 8; ks++) {
            unsigned af[4];
            af[0] = Ps[w * 16 + gid][ks * 8 + tg];
            af[1] = Ps[w * 16 + gid + 8][ks * 8 + tg];
            af[2] = Ps[w * 16 + gid][ks * 8 + tg + 4];
            af[3] = Ps[w * 16 + gid + 8][ks * 8 + tg + 4];
#pragma unroll
            for (int nt = 0; nt < 8; nt++) {
                unsigned bf[2];
                bf[0] = Vs[ks * 8 + tg][nt * 8 + gid];
                bf[1] = Vs[ks * 8 + tg + 4][nt * 8 + gid];
                mma_tf32(o[nt], af, bf);
            }
        }
        __syncthreads();
    }

    // Normalize, RNA-round (proj GEMM consumes raw), write merged [B,S,D]
    float i0 = 1.0f / l0, i1 = 1.0f / l1;
    int r0 = qb * 128 + w * 16 + gid;
    float* p0 = Out + ((size_t)b * 2048 + r0) * 1024 + h * 64;
    float* p1 = p0 + (size_t)8 * 1024;
#pragma unroll
    for (int nt = 0; nt < 8; nt++) {
        *(float2*)(p0 + nt * 8 + 2 * tg) = make_float2(
            __uint_as_float(f2tf32(o[nt][0] * i0)), __uint_as_float(f2tf32(o[nt][1] * i0)));
        *(float2*)(p1 + nt * 8 + 2 * tg) = make_float2(
            __uint_as_float(f2tf32(o[nt][2] * i1)), __uint_as_float(f2tf32(o[nt][3] * i1)));
    }
}

// ---------------------------------------------------------------------------
extern "C" void kernel_launch(void* const* d_in, const int* in_sizes, int n_in,
                              void* d_out, int out_size)
{
    const float* x     = (const float*)d_in[0];
    const float* W_qkv = (const float*)d_in[1];
    const float* b_qkv = (const float*)d_in[2];
    const float* W_out = (const float*)d_in[3];
    const float* b_out = (const float*)d_in[4];
    float* out = (float*)d_out;

    float *attn, *xtf, *wqkv, *wout;
    cudaGetSymbolAddress((void**)&attn, g_attn);
    cudaGetSymbolAddress((void**)&xtf,  g_xtf);
    cudaGetSymbolAddress((void**)&wqkv, g_Wqkv_r);
    cudaGetSymbolAddress((void**)&wout, g_Wout_r);

    // prep: RNA-round activations and weights (elementwise, layout preserved)
    cvt_rna_kernel<<<8192, 256>>>((const float4*)x, (float4*)xtf);
    cvt_rna_kernel<<<3072, 256>>>((const float4*)W_qkv, (float4*)wqkv);
    cvt_rna_kernel<<<1024, 256>>>((const float4*)W_out, (float4*)wout);

    cudaFuncSetAttribute(mma_gemm2<true>,  cudaFuncAttributeMaxDynamicSharedMemorySize, GEMM_SMEM);
    cudaFuncSetAttribute(mma_gemm2<false>, cudaFuncAttributeMaxDynamicSharedMemorySize, GEMM_SMEM);

    // 1) QKV projection (bias + head-split + tf32-round fused in epilogue)
    mma_gemm2<true><<<dim3(24, 64), 256, GEMM_SMEM>>>(xtf, wqkv, b_qkv, nullptr, 3072);

    // 2) causal flash attention
    cudaFuncSetAttribute(flash_mma, cudaFuncAttributeMaxDynamicSharedMemorySize, FLASH_SMEM_BYTES);
    flash_mma<<<dim3(16, 64), 256, FLASH_SMEM_BYTES>>>(attn);

    // 3) output projection (fp32 output, no rounding)
    mma_gemm2<false><<<dim3(8, 64), 256, GEMM_SMEM>>>(attn, wout, b_out, out, 1024);
}

// round 7
// speedup vs baseline: 3.5731x; 1.2027x over previous
#include <cuda_runtime.h>
#include <cstdint>
#include <math.h>

// B=4, S=2048, D=1024, H=16, HD=64, M=8192
#define SCALE_LOG2E 0.18033688011112042f   // (1/8) * log2(e)

// ---------------- scratch (no allocation allowed) ----------------
__device__ float g_Q[4 * 16 * 2048 * 64];     // [B,H,S,HD] tf32-rounded
__device__ float g_K[4 * 16 * 2048 * 64];
__device__ float g_V[4 * 16 * 2048 * 64];
__device__ float g_attn[4 * 2048 * 1024];     // merged [B,S,D], tf32-rounded
__device__ float g_xtf[8192 * 1024];          // x, tf32-rounded
__device__ float g_Wqkv_r[1024 * 3072];       // W_qkv, tf32-rounded
__device__ float g_Wout_r[1024 * 1024];       // W_out, tf32-rounded

// ---------------- helpers ----------------
__device__ __forceinline__ unsigned f2tf32(float f) {
    unsigned r; asm("cvt.rna.tf32.f32 %0, %1;" : "=r"(r) : "f"(f)); return r;
}
__device__ __forceinline__ uint32_t smem_u32(const void* p) {
    uint32_t a;
    asm("{ .reg .u64 t; cvta.to.shared.u64 t, %1; cvt.u32.u64 %0, t; }" : "=r"(a) : "l"(p));
    return a;
}
__device__ __forceinline__ void cp_async16(uint32_t dst, const void* src) {
    asm volatile("cp.async.cg.shared.global [%0], [%1], 16;" :: "r"(dst), "l"(src));
}
#define CP_COMMIT()  asm volatile("cp.async.commit_group;" ::: "memory")
#define CP_WAIT(n)   asm volatile("cp.async.wait_group %0;" :: "n"(n) : "memory")

__device__ __forceinline__ void mma_tf32(float* d, const unsigned* a, const unsigned* b) {
    asm volatile(
        "mma.sync.aligned.m16n8k8.row.col.f32.tf32.tf32.f32 "
        "{%0,%1,%2,%3}, {%4,%5,%6,%7}, {%8,%9}, {%0,%1,%2,%3};"
        : "+f"(d[0]), "+f"(d[1]), "+f"(d[2]), "+f"(d[3])
        : "r"(a[0]), "r"(a[1]), "r"(a[2]), "r"(a[3]), "r"(b[0]), "r"(b[1]));
}

// ---------------- prep: elementwise RNA rounding ----------------
__global__ void cvt_rna_kernel(const float4* __restrict__ in, float4* __restrict__ out) {
    int i = blockIdx.x * blockDim.x + threadIdx.x;
    float4 v = in[i];
    out[i] = make_float4(__uint_as_float(f2tf32(v.x)), __uint_as_float(f2tf32(v.y)),
                         __uint_as_float(f2tf32(v.z)), __uint_as_float(f2tf32(v.w)));
}

// ---------------- TF32 mma GEMM, BK=32, 2-stage cp.async ring ----------------
// C[M,N] = A[M,1024] @ B[1024,N] + bias. 128x128 CTA tile, 256 threads,
// warps 2x4, warp tile 64x32. As[m][k] stride 36, Bs[k][n] stride 136.
#define GK 1024
#define NSTEPS 32
#define AS_F (128 * 36)          // 4608
#define BS_F (32 * 136)          // 4352
#define STAGE_F (AS_F + BS_F)    // 8960
#define STAGE_BYTES (STAGE_F * 4)
#define GEMM_SMEM (2 * STAGE_BYTES)   // 71680

template <bool SPLIT>
__global__ __launch_bounds__(256, 2)
void mma_gemm2(const float* __restrict__ A, const float* __restrict__ Bm,
               const float* __restrict__ bias, float* __restrict__ C, int N)
{
    extern __shared__ unsigned smu[];
    const uint32_t sbase = smem_u32(smu);

    const int tid  = threadIdx.x;
    const int lane = tid & 31;
    const int warp = tid >> 5;
    const int gid  = lane >> 2, tg = lane & 3;
    const int wm   = warp >> 2, wn = warp & 3;
    const int rowBase = blockIdx.y * 128;
    const int colBase = blockIdx.x * 128;

    float acc[4][4][4];
#pragma unroll
    for (int mt = 0; mt < 4; mt++)
#pragma unroll
        for (int nt = 0; nt < 4; nt++)
#pragma unroll
            for (int r = 0; r < 4; r++) acc[mt][nt][r] = 0.0f;

    auto fill = [&](int s, int k0) {
        uint32_t sA = sbase + s * STAGE_BYTES;
        uint32_t sB = sA + AS_F * 4;
        // A: 128 rows x 32 floats (8 x 16B chunks per row)
#pragma unroll
        for (int i = 0; i < 4; i++) {
            int f = tid + (i << 8);
            int r = f >> 3, c = f & 7;
            cp_async16(sA + r * 144 + c * 16, A + (size_t)(rowBase + r) * GK + k0 + c * 4);
        }
        // B: 32 rows x 128 floats (32 x 16B chunks per row)
#pragma unroll
        for (int i = 0; i < 4; i++) {
            int f = tid + (i << 8);
            int r = f >> 5, c = f & 31;
            cp_async16(sB + r * 544 + c * 16, Bm + (size_t)(k0 + r) * N + colBase + c * 4);
        }
        CP_COMMIT();
    };

    auto compute = [&](int s) {
        const unsigned* As = smu + s * STAGE_F;
        const unsigned* Bs = As + AS_F;
#pragma unroll
        for (int ks = 0; ks < 4; ks++) {
            unsigned af[4][4];
#pragma unroll
            for (int mt = 0; mt < 4; mt++) {
                int r0 = (wm * 64 + mt * 16 + gid) * 36 + ks * 8 + tg;
                af[mt][0] = As[r0];
                af[mt][1] = As[r0 + 288];   // +8 rows
                af[mt][2] = As[r0 + 4];     // +4 k
                af[mt][3] = As[r0 + 292];
            }
            unsigned bf[4][2];
#pragma unroll
            for (int nt = 0; nt < 4; nt++) {
                int c0 = (ks * 8 + tg) * 136 + wn * 32 + nt * 8 + gid;
                bf[nt][0] = Bs[c0];
                bf[nt][1] = Bs[c0 + 544];   // +4 k rows
            }
#pragma unroll
            for (int mt = 0; mt < 4; mt++)
#pragma unroll
                for (int nt = 0; nt < 4; nt++)
                    mma_tf32(acc[mt][nt], af[mt], bf[nt]);
        }
    };

    fill(0, 0);
    fill(1, 32);

#pragma unroll 1
    for (int i = 0; i < NSTEPS; i++) {
        if (i == NSTEPS - 1) { CP_WAIT(0); } else { CP_WAIT(1); }
        __syncthreads();
        compute(i & 1);
        __syncthreads();
        if (i + 2 < NSTEPS) fill(i & 1, (i + 2) * 32);
    }

    // Epilogue
#pragma unroll
    for (int mt = 0; mt < 4; mt++) {
        int m = rowBase + wm * 64 + mt * 16 + gid;
#pragma unroll
        for (int nt = 0; nt < 4; nt++) {
            int n = colBase + wn * 32 + nt * 8 + 2 * tg;
            float2 bv = *(const float2*)(bias + n);
            float2 v0 = make_float2(acc[mt][nt][0] + bv.x, acc[mt][nt][1] + bv.y);
            float2 v1 = make_float2(acc[mt][nt][2] + bv.x, acc[mt][nt][3] + bv.y);
            if (SPLIT) {
                v0.x = __uint_as_float(f2tf32(v0.x)); v0.y = __uint_as_float(f2tf32(v0.y));
                v1.x = __uint_as_float(f2tf32(v1.x)); v1.y = __uint_as_float(f2tf32(v1.y));
                const int part = n >> 10, dcol = n & 1023;
                const int hh = dcol >> 6, hd = dcol & 63;
                float* dst = (part == 0) ? g_Q : (part == 1) ? g_K : g_V;
                {
                    int bb = m >> 11, si = m & 2047;
                    *(float2*)(dst + ((((size_t)bb * 16 + hh) * 2048 + si) * 64 + hd)) = v0;
                }
                {
                    int m2 = m + 8, bb = m2 >> 11, si = m2 & 2047;
                    *(float2*)(dst + ((((size_t)bb * 16 + hh) * 2048 + si) * 64 + hd)) = v1;
                }
            } else {
                *(float2*)(C + (size_t)m * N + n) = v0;
                *(float2*)(C + (size_t)(m + 8) * N + n) = v1;
            }
        }
    }
}

// ---------------- causal flash attention ----------------
// BM=128, BN=64, 256 threads. P round-trip replaced with intra-quad shuffles
// (no Ps smem) -> 70.7KB smem -> 2 CTAs/SM. Large-qb blocks scheduled first.
#define FLASH_SMEM_BYTES ((128 * 68 + 64 * 68 + 64 * 72) * 4)

__global__ __launch_bounds__(256, 2)
void flash_mma(float* __restrict__ Out)
{
    extern __shared__ unsigned sm[];
    unsigned (*Qs)[68] = (unsigned(*)[68])sm;
    unsigned (*Ks)[68] = (unsigned(*)[68])(sm + 128 * 68);
    unsigned (*Vs)[72] = (unsigned(*)[72])(sm + 128 * 68 + 64 * 68);

    const int qb = (gridDim.x - 1) - blockIdx.x;   // big tiles first
    const int bh = blockIdx.y;
    const int b = bh >> 4, h = bh & 15;
    const int tid = threadIdx.x, lane = tid & 31, w = tid >> 5;
    const int gid = lane >> 2, tg = lane & 3;

    const float* Qg = g_Q + ((size_t)bh * 2048 + qb * 128) * 64;
    const float* Kg = g_K + (size_t)bh * 2048 * 64;
    const float* Vg = g_V + (size_t)bh * 2048 * 64;

    // Q: scale into exp2 domain + RNA round
#pragma unroll
    for (int j = 0; j < 8; j++) {
        int f = tid + 256 * j;
        int r = f >> 4, c4 = (f & 15) * 4;
        float4 v = *(const float4*)(Qg + r * 64 + c4);
        uint4 u = make_uint4(f2tf32(v.x * SCALE_LOG2E), f2tf32(v.y * SCALE_LOG2E),
                             f2tf32(v.z * SCALE_LOG2E), f2tf32(v.w * SCALE_LOG2E));
        *(uint4*)&Qs[r][c4] = u;
    }

    float m0 = -1e30f, m1 = -1e30f, l0 = 0.0f, l1 = 0.0f;
    float o[8][4];
#pragma unroll
    for (int nt = 0; nt < 8; nt++)
#pragma unroll
        for (int r = 0; r < 4; r++) o[nt][r] = 0.0f;

    const int ktmax = 2 * qb + 1;
    for (int kt = 0; kt <= ktmax; kt++) {
        // K/V already tf32 values: raw copies
#pragma unroll
        for (int j = 0; j < 4; j++) {
            int f = tid + 256 * j;
            int r = f >> 4, c4 = (f & 15) * 4;
            uint4 kv = *(const uint4*)(Kg + ((size_t)kt * 64 + r) * 64 + c4);
            *(uint4*)&Ks[r][c4] = kv;
            uint4 vv = *(const uint4*)(Vg + ((size_t)kt * 64 + r) * 64 + c4);
            *(uint4*)&Vs[r][c4] = vv;
        }
        __syncthreads();

        float sacc[8][4];
#pragma unroll
        for (int nt = 0; nt < 8; nt++)
#pragma unroll
            for (int r = 0; r < 4; r++) sacc[nt][r] = 0.0f;

#pragma unroll
        for (int ks = 0; ks < 8; ks++) {
            unsigned af[4];
            af[0] = Qs[w * 16 + gid][ks * 8 + tg];
            af[1] = Qs[w * 16 + gid + 8][ks * 8 + tg];
            af[2] = Qs[w * 16 + gid][ks * 8 + tg + 4];
            af[3] = Qs[w * 16 + gid + 8][ks * 8 + tg + 4];
#pragma unroll
            for (int nt = 0; nt < 8; nt++) {
                unsigned bf[2];
                bf[0] = Ks[nt * 8 + gid][ks * 8 + tg];
                bf[1] = Ks[nt * 8 + gid][ks * 8 + tg + 4];
                mma_tf32(sacc[nt], af, bf);
            }
        }

        if (kt >= 2 * qb) {
            int r0 = qb * 128 + w * 16 + gid;
            int r1 = r0 + 8;
#pragma unroll
            for (int nt = 0; nt < 8; nt++) {
                int c = kt * 64 + nt * 8 + 2 * tg;
                if (c > r0)     sacc[nt][0] = -1e30f;
                if (c + 1 > r0) sacc[nt][1] = -1e30f;
                if (c > r1)     sacc[nt][2] = -1e30f;
                if (c + 1 > r1) sacc[nt][3] = -1e30f;
            }
        }

        // online softmax (exp2 domain), quad reductions
        float mx0 = -1e30f, mx1 = -1e30f;
#pragma unroll
        for (int nt = 0; nt < 8; nt++) {
            mx0 = fmaxf(mx0, fmaxf(sacc[nt][0], sacc[nt][1]));
            mx1 = fmaxf(mx1, fmaxf(sacc[nt][2], sacc[nt][3]));
        }
        mx0 = fmaxf(mx0, __shfl_xor_sync(0xffffffffu, mx0, 1));
        mx0 = fmaxf(mx0, __shfl_xor_sync(0xffffffffu, mx0, 2));
        mx1 = fmaxf(mx1, __shfl_xor_sync(0xffffffffu, mx1, 1));
        mx1 = fmaxf(mx1, __shfl_xor_sync(0xffffffffu, mx1, 2));
        float mn0 = fmaxf(m0, mx0), mn1 = fmaxf(m1, mx1);
        float a0 = exp2f(m0 - mn0), a1 = exp2f(m1 - mn1);
        m0 = mn0; m1 = mn1;
        float rs0 = 0.0f, rs1 = 0.0f;
#pragma unroll
        for (int nt = 0; nt < 8; nt++) {
            sacc[nt][0] = exp2f(sacc[nt][0] - mn0); rs0 += sacc[nt][0];
            sacc[nt][1] = exp2f(sacc[nt][1] - mn0); rs0 += sacc[nt][1];
            sacc[nt][2] = exp2f(sacc[nt][2] - mn1); rs1 += sacc[nt][2];
            sacc[nt][3] = exp2f(sacc[nt][3] - mn1); rs1 += sacc[nt][3];
        }
        rs0 += __shfl_xor_sync(0xffffffffu, rs0, 1);
        rs0 += __shfl_xor_sync(0xffffffffu, rs0, 2);
        rs1 += __shfl_xor_sync(0xffffffffu, rs1, 1);
        rs1 += __shfl_xor_sync(0xffffffffu, rs1, 2);
        l0 = l0 * a0 + rs0;
        l1 = l1 * a1 + rs1;
#pragma unroll
        for (int nt = 0; nt < 8; nt++) {
            o[nt][0] *= a0; o[nt][1] *= a0; o[nt][2] *= a1; o[nt][3] *= a1;
        }

        // PV: A-fragment of P reconstructed via intra-quad shuffles.
        // Col c of row g lives in lane 4g + c/2, element (c&1) (rows g / g+8).
#pragma unroll
        for (int ks = 0; ks < 8; ks++) {
            int s0 = (lane & ~3) | (tg >> 1);
            int s1 = s0 + 2;
            float e0 = __shfl_sync(0xffffffffu, sacc[ks][0], s0);
            float e1 = __shfl_sync(0xffffffffu, sacc[ks][1], s0);
            float e2 = __shfl_sync(0xffffffffu, sacc[ks][2], s0);
            float e3 = __shfl_sync(0xffffffffu, sacc[ks][3], s0);
            float f0 = __shfl_sync(0xffffffffu, sacc[ks][0], s1);
            float f1 = __shfl_sync(0xffffffffu, sacc[ks][1], s1);
            float f2 = __shfl_sync(0xffffffffu, sacc[ks][2], s1);
            float f3 = __shfl_sync(0xffffffffu, sacc[ks][3], s1);
            bool odd = (tg & 1);
            unsigned af[4];
            af[0] = f2tf32(odd ? e1 : e0);   // P[g   ][8ks+tg]
            af[1] = f2tf32(odd ? e3 : e2);   // P[g+8 ][8ks+tg]
            af[2] = f2tf32(odd ? f1 : f0);   // P[g   ][8ks+tg+4]
            af[3] = f2tf32(odd ? f3 : f2);   // P[g+8 ][8ks+tg+4]
#pragma unroll
            for (int nt = 0; nt < 8; nt++) {
                unsigned bf[2];
                bf[0] = Vs[ks * 8 + tg][nt * 8 + gid];
                bf[1] = Vs[ks * 8 + tg + 4][nt * 8 + gid];
                mma_tf32(o[nt], af, bf);
            }
        }
        __syncthreads();
    }

    // Normalize, RNA-round, write merged [B,S,D]
    float i0 = 1.0f / l0, i1 = 1.0f / l1;
    int r0 = qb * 128 + w * 16 + gid;
    float* p0 = Out + ((size_t)b * 2048 + r0) * 1024 + h * 64;
    float* p1 = p0 + (size_t)8 * 1024;
#pragma unroll
    for (int nt = 0; nt < 8; nt++) {
        *(float2*)(p0 + nt * 8 + 2 * tg) = make_float2(
            __uint_as_float(f2tf32(o[nt][0] * i0)), __uint_as_float(f2tf32(o[nt][1] * i0)));
        *(float2*)(p1 + nt * 8 + 2 * tg) = make_float2(
            __uint_as_float(f2tf32(o[nt][2] * i1)), __uint_as_float(f2tf32(o[nt][3] * i1)));
    }
}

// ---------------------------------------------------------------------------
extern "C" void kernel_launch(void* const* d_in, const int* in_sizes, int n_in,
                              void* d_out, int out_size)
{
    const float* x     = (const float*)d_in[0];
    const float* W_qkv = (const float*)d_in[1];
    const float* b_qkv = (const float*)d_in[2];
    const float* W_out = (const float*)d_in[3];
    const float* b_out = (const float*)d_in[4];
    float* out = (float*)d_out;

    float *attn, *xtf, *wqkv, *wout;
    cudaGetSymbolAddress((void**)&attn, g_attn);
    cudaGetSymbolAddress((void**)&xtf,  g_xtf);
    cudaGetSymbolAddress((void**)&wqkv, g_Wqkv_r);
    cudaGetSymbolAddress((void**)&wout, g_Wout_r);

    // prep: RNA-round activations and weights
    cvt_rna_kernel<<<8192, 256>>>((const float4*)x, (float4*)xtf);
    cvt_rna_kernel<<<3072, 256>>>((const float4*)W_qkv, (float4*)wqkv);
    cvt_rna_kernel<<<1024, 256>>>((const float4*)W_out, (float4*)wout);

    cudaFuncSetAttribute(mma_gemm2<true>,  cudaFuncAttributeMaxDynamicSharedMemorySize, GEMM_SMEM);
    cudaFuncSetAttribute(mma_gemm2<false>, cudaFuncAttributeMaxDynamicSharedMemorySize, GEMM_SMEM);

    // 1) QKV projection
    mma_gemm2<true><<<dim3(24, 64), 256, GEMM_SMEM>>>(xtf, wqkv, b_qkv, nullptr, 3072);

    // 2) causal flash attention
    cudaFuncSetAttribute(flash_mma, cudaFuncAttributeMaxDynamicSharedMemorySize, FLASH_SMEM_BYTES);
    flash_mma<<<dim3(16, 64), 256, FLASH_SMEM_BYTES>>>(attn);

    // 3) output projection
    mma_gemm2<false><<<dim3(8, 64), 256, GEMM_SMEM>>>(attn, wout, b_out, out, 1024);
}

// round 8
// speedup vs baseline: 3.6594x; 1.0241x over previous
#include <cuda_runtime.h>
#include <cstdint>
#include <math.h>

// B=4, S=2048, D=1024, H=16, HD=64, M=8192
#define SCALE_LOG2E 0.18033688011112042f   // (1/8) * log2(e)

// ---------------- scratch (no allocation allowed) ----------------
__device__ float g_Q[4 * 16 * 2048 * 64];     // [B,H,S,HD] tf32-rounded
__device__ float g_K[4 * 16 * 2048 * 64];
__device__ float g_V[4 * 16 * 2048 * 64];
__device__ float g_attn[4 * 2048 * 1024];     // merged [B,S,D], tf32-rounded
__device__ float g_xtf[8192 * 1024];          // x, tf32-rounded
__device__ float g_Wqkv_r[1024 * 3072];       // W_qkv, tf32-rounded
__device__ float g_Wout_r[1024 * 1024];       // W_out, tf32-rounded

// ---------------- helpers ----------------
__device__ __forceinline__ unsigned f2tf32(float f) {
    unsigned r; asm("cvt.rna.tf32.f32 %0, %1;" : "=r"(r) : "f"(f)); return r;
}
__device__ __forceinline__ uint32_t smem_u32(const void* p) {
    uint32_t a;
    asm("{ .reg .u64 t; cvta.to.shared.u64 t, %1; cvt.u32.u64 %0, t; }" : "=r"(a) : "l"(p));
    return a;
}
__device__ __forceinline__ void cp_async16(uint32_t dst, const void* src) {
    asm volatile("cp.async.cg.shared.global [%0], [%1], 16;" :: "r"(dst), "l"(src));
}
#define CP_COMMIT()  asm volatile("cp.async.commit_group;" ::: "memory")
#define CP_WAIT(n)   asm volatile("cp.async.wait_group %0;" :: "n"(n) : "memory")

__device__ __forceinline__ void mma_tf32(float* d, const unsigned* a, const unsigned* b) {
    asm volatile(
        "mma.sync.aligned.m16n8k8.row.col.f32.tf32.tf32.f32 "
        "{%0,%1,%2,%3}, {%4,%5,%6,%7}, {%8,%9}, {%0,%1,%2,%3};"
        : "+f"(d[0]), "+f"(d[1]), "+f"(d[2]), "+f"(d[3])
        : "r"(a[0]), "r"(a[1]), "r"(a[2]), "r"(a[3]), "r"(b[0]), "r"(b[1]));
}

// ---------------- prep: elementwise RNA rounding ----------------
__global__ void cvt_rna_kernel(const float4* __restrict__ in, float4* __restrict__ out) {
    int i = blockIdx.x * blockDim.x + threadIdx.x;
    float4 v = in[i];
    out[i] = make_float4(__uint_as_float(f2tf32(v.x)), __uint_as_float(f2tf32(v.y)),
                         __uint_as_float(f2tf32(v.z)), __uint_as_float(f2tf32(v.w)));
}

// ---------------- TF32 mma GEMM, BK=32, 3-stage ring, 1 barrier/iter ------
// C[M,N] = A[M,1024] @ B[1024,N] + bias. 128x128 CTA tile, 256 threads,
// warps 2x4, warp tile 64x32. As[m][k] stride 36, Bs[k][n] stride 136.
#define GK 1024
#define NSTEPS 32
#define AS_F (128 * 36)          // 4608
#define BS_F (32 * 136)          // 4352
#define STAGE_F (AS_F + BS_F)    // 8960
#define STAGE_BYTES (STAGE_F * 4)
#define GEMM_SMEM (3 * STAGE_BYTES)   // 107520

template <bool SPLIT>
__global__ __launch_bounds__(256, 2)
void mma_gemm2(const float* __restrict__ A, const float* __restrict__ Bm,
               const float* __restrict__ bias, float* __restrict__ C, int N)
{
    extern __shared__ unsigned smu[];
    const uint32_t sbase = smem_u32(smu);

    const int tid  = threadIdx.x;
    const int lane = tid & 31;
    const int warp = tid >> 5;
    const int gid  = lane >> 2, tg = lane & 3;
    const int wm   = warp >> 2, wn = warp & 3;
    const int rowBase = blockIdx.y * 128;
    const int colBase = blockIdx.x * 128;

    float acc[4][4][4];
#pragma unroll
    for (int mt = 0; mt < 4; mt++)
#pragma unroll
        for (int nt = 0; nt < 4; nt++)
#pragma unroll
            for (int r = 0; r < 4; r++) acc[mt][nt][r] = 0.0f;

    auto fill = [&](int s, int k0) {
        uint32_t sA = sbase + s * STAGE_BYTES;
        uint32_t sB = sA + AS_F * 4;
#pragma unroll
        for (int i = 0; i < 4; i++) {
            int f = tid + (i << 8);
            int r = f >> 3, c = f & 7;
            cp_async16(sA + r * 144 + c * 16, A + (size_t)(rowBase + r) * GK + k0 + c * 4);
        }
#pragma unroll
        for (int i = 0; i < 4; i++) {
            int f = tid + (i << 8);
            int r = f >> 5, c = f & 31;
            cp_async16(sB + r * 544 + c * 16, Bm + (size_t)(k0 + r) * N + colBase + c * 4);
        }
        CP_COMMIT();
    };

    auto compute = [&](int s) {
        const unsigned* As = smu + s * STAGE_F;
        const unsigned* Bs = As + AS_F;
#pragma unroll
        for (int ks = 0; ks < 4; ks++) {
            unsigned af[4][4];
#pragma unroll
            for (int mt = 0; mt < 4; mt++) {
                int r0 = (wm * 64 + mt * 16 + gid) * 36 + ks * 8 + tg;
                af[mt][0] = As[r0];
                af[mt][1] = As[r0 + 288];   // +8 rows
                af[mt][2] = As[r0 + 4];     // +4 k
                af[mt][3] = As[r0 + 292];
            }
            unsigned bf[4][2];
#pragma unroll
            for (int nt = 0; nt < 4; nt++) {
                int c0 = (ks * 8 + tg) * 136 + wn * 32 + nt * 8 + gid;
                bf[nt][0] = Bs[c0];
                bf[nt][1] = Bs[c0 + 544];   // +4 k rows
            }
#pragma unroll
            for (int mt = 0; mt < 4; mt++)
#pragma unroll
                for (int nt = 0; nt < 4; nt++)
                    mma_tf32(acc[mt][nt], af[mt], bf[nt]);
        }
    };

    fill(0, 0);
    fill(1, 32);

    int s = 0, sf = 2;
#pragma unroll 1
    for (int i = 0; i < NSTEPS; i++) {
        if (i == NSTEPS - 1) { CP_WAIT(0); } else { CP_WAIT(1); }
        __syncthreads();
        // fill stage (i+2)%3: no warp in this barrier interval reads it
        if (i + 2 < NSTEPS) {
            fill(sf, (i + 2) * 32);
            sf = (sf == 2) ? 0 : sf + 1;
        }
        compute(s);
        s = (s == 2) ? 0 : s + 1;
    }

    // Epilogue
#pragma unroll
    for (int mt = 0; mt < 4; mt++) {
        int m = rowBase + wm * 64 + mt * 16 + gid;
#pragma unroll
        for (int nt = 0; nt < 4; nt++) {
            int n = colBase + wn * 32 + nt * 8 + 2 * tg;
            float2 bv = *(const float2*)(bias + n);
            float2 v0 = make_float2(acc[mt][nt][0] + bv.x, acc[mt][nt][1] + bv.y);
            float2 v1 = make_float2(acc[mt][nt][2] + bv.x, acc[mt][nt][3] + bv.y);
            if (SPLIT) {
                v0.x = __uint_as_float(f2tf32(v0.x)); v0.y = __uint_as_float(f2tf32(v0.y));
                v1.x = __uint_as_float(f2tf32(v1.x)); v1.y = __uint_as_float(f2tf32(v1.y));
                const int part = n >> 10, dcol = n & 1023;
                const int hh = dcol >> 6, hd = dcol & 63;
                float* dst = (part == 0) ? g_Q : (part == 1) ? g_K : g_V;
                {
                    int bb = m >> 11, si = m & 2047;
                    *(float2*)(dst + ((((size_t)bb * 16 + hh) * 2048 + si) * 64 + hd)) = v0;
                }
                {
                    int m2 = m + 8, bb = m2 >> 11, si = m2 & 2047;
                    *(float2*)(dst + ((((size_t)bb * 16 + hh) * 2048 + si) * 64 + hd)) = v1;
                }
            } else {
                *(float2*)(C + (size_t)m * N + n) = v0;
                *(float2*)(C + (size_t)(m + 8) * N + n) = v1;
            }
        }
    }
}

// ---------------- causal flash attention ----------------
// BM=128, BN=64, 256 threads, 2 CTAs/SM. K/V double-buffered via cp.async
// (prefetch depth 1), single barrier per tile. P via intra-quad shuffles.
#define Q_F (128 * 68)           // 8704
#define KV_K_F (64 * 68)         // 4352
#define KV_V_F (64 * 72)         // 4608
#define KV_STAGE_F (KV_K_F + KV_V_F)   // 8960
#define FLASH_SMEM_BYTES ((Q_F + 2 * KV_STAGE_F) * 4)   // 106496

__global__ __launch_bounds__(256, 2)
void flash_mma(float* __restrict__ Out)
{
    extern __shared__ unsigned sm[];
    unsigned (*Qs)[68] = (unsigned(*)[68])sm;
    const uint32_t sbase = smem_u32(sm);

    const int qb = (gridDim.x - 1) - blockIdx.x;   // big tiles first
    const int bh = blockIdx.y;
    const int b = bh >> 4, h = bh & 15;
    const int tid = threadIdx.x, lane = tid & 31, w = tid >> 5;
    const int gid = lane >> 2, tg = lane & 3;

    const float* Qg = g_Q + ((size_t)bh * 2048 + qb * 128) * 64;
    const float* Kg = g_K + (size_t)bh * 2048 * 64;
    const float* Vg = g_V + (size_t)bh * 2048 * 64;

    auto fill_kv = [&](int s, int kt) {
        uint32_t kb = sbase + (Q_F + s * KV_STAGE_F) * 4;
        uint32_t vb = kb + KV_K_F * 4;
        const float* Kp = Kg + (size_t)kt * 4096;
        const float* Vp = Vg + (size_t)kt * 4096;
#pragma unroll
        for (int j = 0; j < 4; j++) {
            int f = tid + 256 * j;
            int r = f >> 4, c = f & 15;
            cp_async16(kb + r * 272 + c * 16, Kp + r * 64 + c * 4);
            cp_async16(vb + r * 288 + c * 16, Vp + r * 64 + c * 4);
        }
        CP_COMMIT();
    };

    // Q: scale into exp2 domain + RNA round
#pragma unroll
    for (int j = 0; j < 8; j++) {
        int f = tid + 256 * j;
        int r = f >> 4, c4 = (f & 15) * 4;
        float4 v = *(const float4*)(Qg + r * 64 + c4);
        uint4 u = make_uint4(f2tf32(v.x * SCALE_LOG2E), f2tf32(v.y * SCALE_LOG2E),
                             f2tf32(v.z * SCALE_LOG2E), f2tf32(v.w * SCALE_LOG2E));
        *(uint4*)&Qs[r][c4] = u;
    }

    float m0 = -1e30f, m1 = -1e30f, l0 = 0.0f, l1 = 0.0f;
    float o[8][4];
#pragma unroll
    for (int nt = 0; nt < 8; nt++)
#pragma unroll
        for (int r = 0; r < 4; r++) o[nt][r] = 0.0f;

    const int ktmax = 2 * qb + 1;
    fill_kv(0, 0);

    for (int kt = 0; kt <= ktmax; kt++) {
        CP_WAIT(0);
        __syncthreads();
        // prefetch next tile into the opposite stage (overlaps compute)
        if (kt < ktmax) fill_kv((kt + 1) & 1, kt + 1);

        const unsigned* Ksp = sm + Q_F + (kt & 1) * KV_STAGE_F;
        const unsigned* Vsp = Ksp + KV_K_F;

        float sacc[8][4];
#pragma unroll
        for (int nt = 0; nt < 8; nt++)
#pragma unroll
            for (int r = 0; r < 4; r++) sacc[nt][r] = 0.0f;

#pragma unroll
        for (int ks = 0; ks < 8; ks++) {
            unsigned af[4];
            af[0] = Qs[w * 16 + gid][ks * 8 + tg];
            af[1] = Qs[w * 16 + gid + 8][ks * 8 + tg];
            af[2] = Qs[w * 16 + gid][ks * 8 + tg + 4];
            af[3] = Qs[w * 16 + gid + 8][ks * 8 + tg + 4];
#pragma unroll
            for (int nt = 0; nt < 8; nt++) {
                unsigned bf[2];
                bf[0] = Ksp[(nt * 8 + gid) * 68 + ks * 8 + tg];
                bf[1] = Ksp[(nt * 8 + gid) * 68 + ks * 8 + tg + 4];
                mma_tf32(sacc[nt], af, bf);
            }
        }

        if (kt >= 2 * qb) {
            int r0 = qb * 128 + w * 16 + gid;
            int r1 = r0 + 8;
#pragma unroll
            for (int nt = 0; nt < 8; nt++) {
                int c = kt * 64 + nt * 8 + 2 * tg;
                if (c > r0)     sacc[nt][0] = -1e30f;
                if (c + 1 > r0) sacc[nt][1] = -1e30f;
                if (c > r1)     sacc[nt][2] = -1e30f;
                if (c + 1 > r1) sacc[nt][3] = -1e30f;
            }
        }

        // online softmax (exp2 domain), quad reductions
        float mx0 = -1e30f, mx1 = -1e30f;
#pragma unroll
        for (int nt = 0; nt < 8; nt++) {
            mx0 = fmaxf(mx0, fmaxf(sacc[nt][0], sacc[nt][1]));
            mx1 = fmaxf(mx1, fmaxf(sacc[nt][2], sacc[nt][3]));
        }
        mx0 = fmaxf(mx0, __shfl_xor_sync(0xffffffffu, mx0, 1));
        mx0 = fmaxf(mx0, __shfl_xor_sync(0xffffffffu, mx0, 2));
        mx1 = fmaxf(mx1, __shfl_xor_sync(0xffffffffu, mx1, 1));
        mx1 = fmaxf(mx1, __shfl_xor_sync(0xffffffffu, mx1, 2));
        float mn0 = fmaxf(m0, mx0), mn1 = fmaxf(m1, mx1);
        float a0 = exp2f(m0 - mn0), a1 = exp2f(m1 - mn1);
        m0 = mn0; m1 = mn1;
        float rs0 = 0.0f, rs1 = 0.0f;
#pragma unroll
        for (int nt = 0; nt < 8; nt++) {
            sacc[nt][0] = exp2f(sacc[nt][0] - mn0); rs0 += sacc[nt][0];
            sacc[nt][1] = exp2f(sacc[nt][1] - mn0); rs0 += sacc[nt][1];
            sacc[nt][2] = exp2f(sacc[nt][2] - mn1); rs1 += sacc[nt][2];
            sacc[nt][3] = exp2f(sacc[nt][3] - mn1); rs1 += sacc[nt][3];
        }
        rs0 += __shfl_xor_sync(0xffffffffu, rs0, 1);
        rs0 += __shfl_xor_sync(0xffffffffu, rs0, 2);
        rs1 += __shfl_xor_sync(0xffffffffu, rs1, 1);
        rs1 += __shfl_xor_sync(0xffffffffu, rs1, 2);
        l0 = l0 * a0 + rs0;
        l1 = l1 * a1 + rs1;
#pragma unroll
        for (int nt = 0; nt < 8; nt++) {
            o[nt][0] *= a0; o[nt][1] *= a0; o[nt][2] *= a1; o[nt][3] *= a1;
        }

        // PV: A-fragment of P via intra-quad shuffles
        int s0 = (lane & ~3) | (tg >> 1);
        int s1 = s0 + 2;
        bool odd = (tg & 1);
#pragma unroll
        for (int ks = 0; ks < 8; ks++) {
            float e0 = __shfl_sync(0xffffffffu, sacc[ks][0], s0);
            float e1 = __shfl_sync(0xffffffffu, sacc[ks][1], s0);
            float e2 = __shfl_sync(0xffffffffu, sacc[ks][2], s0);
            float e3 = __shfl_sync(0xffffffffu, sacc[ks][3], s0);
            float f0 = __shfl_sync(0xffffffffu, sacc[ks][0], s1);
            float f1 = __shfl_sync(0xffffffffu, sacc[ks][1], s1);
            float f2 = __shfl_sync(0xffffffffu, sacc[ks][2], s1);
            float f3 = __shfl_sync(0xffffffffu, sacc[ks][3], s1);
            unsigned af[4];
            af[0] = f2tf32(odd ? e1 : e0);
            af[1] = f2tf32(odd ? e3 : e2);
            af[2] = f2tf32(odd ? f1 : f0);
            af[3] = f2tf32(odd ? f3 : f2);
#pragma unroll
            for (int nt = 0; nt < 8; nt++) {
                unsigned bf[2];
                bf[0] = Vsp[(ks * 8 + tg) * 72 + nt * 8 + gid];
                bf[1] = Vsp[(ks * 8 + tg + 4) * 72 + nt * 8 + gid];
                mma_tf32(o[nt], af, bf);
            }
        }
    }

    // Normalize, RNA-round, write merged [B,S,D]
    float i0 = 1.0f / l0, i1 = 1.0f / l1;
    int r0 = qb * 128 + w * 16 + gid;
    float* p0 = Out + ((size_t)b * 2048 + r0) * 1024 + h * 64;
    float* p1 = p0 + (size_t)8 * 1024;
#pragma unroll
    for (int nt = 0; nt < 8; nt++) {
        *(float2*)(p0 + nt * 8 + 2 * tg) = make_float2(
            __uint_as_float(f2tf32(o[nt][0] * i0)), __uint_as_float(f2tf32(o[nt][1] * i0)));
        *(float2*)(p1 + nt * 8 + 2 * tg) = make_float2(
            __uint_as_float(f2tf32(o[nt][2] * i1)), __uint_as_float(f2tf32(o[nt][3] * i1)));
    }
}

// ---------------------------------------------------------------------------
extern "C" void kernel_launch(void* const* d_in, const int* in_sizes, int n_in,
                              void* d_out, int out_size)
{
    const float* x     = (const float*)d_in[0];
    const float* W_qkv = (const float*)d_in[1];
    const float* b_qkv = (const float*)d_in[2];
    const float* W_out = (const float*)d_in[3];
    const float* b_out = (const float*)d_in[4];
    float* out = (float*)d_out;

    float *attn, *xtf, *wqkv, *wout;
    cudaGetSymbolAddress((void**)&attn, g_attn);
    cudaGetSymbolAddress((void**)&xtf,  g_xtf);
    cudaGetSymbolAddress((void**)&wqkv, g_Wqkv_r);
    cudaGetSymbolAddress((void**)&wout, g_Wout_r);

    // prep: RNA-round activations and weights
    cvt_rna_kernel<<<8192, 256>>>((const float4*)x, (float4*)xtf);
    cvt_rna_kernel<<<3072, 256>>>((const float4*)W_qkv, (float4*)wqkv);
    cvt_rna_kernel<<<1024, 256>>>((const float4*)W_out, (float4*)wout);

    cudaFuncSetAttribute(mma_gemm2<true>,  cudaFuncAttributeMaxDynamicSharedMemorySize, GEMM_SMEM);
    cudaFuncSetAttribute(mma_gemm2<false>, cudaFuncAttributeMaxDynamicSharedMemorySize, GEMM_SMEM);

    // 1) QKV projection
    mma_gemm2<true><<<dim3(24, 64), 256, GEMM_SMEM>>>(xtf, wqkv, b_qkv, nullptr, 3072);

    // 2) causal flash attention
    cudaFuncSetAttribute(flash_mma, cudaFuncAttributeMaxDynamicSharedMemorySize, FLASH_SMEM_BYTES);
    flash_mma<<<dim3(16, 64), 256, FLASH_SMEM_BYTES>>>(attn);

    // 3) output projection
    mma_gemm2<false><<<dim3(8, 64), 256, GEMM_SMEM>>>(attn, wout, b_out, out, 1024);
}

// round 10
// speedup vs baseline: 6.0893x; 1.6640x over previous
#include <cuda_runtime.h>
#include <cuda_fp16.h>
#include <cstdint>
#include <math.h>

// B=4, S=2048, D=1024, H=16, HD=64, M=8192
#define SCALE_LOG2E 0.18033688011112042f   // (1/8) * log2(e)

// ---------------- scratch (no allocation allowed) ----------------
__device__ __half g_Q [4 * 16 * 2048 * 64];   // [B,H,S,HD], pre-scaled by SCALE_LOG2E
__device__ __half g_K [4 * 16 * 2048 * 64];   // [B,H,S,HD]
__device__ __half g_Vt[4 * 16 * 64 * 2048];   // [B,H,HD,S]  (transposed V)
__device__ __half g_attn[4 * 2048 * 1024];    // merged [B,S,D]
__device__ __half g_xh[8192 * 1024];          // x -> fp16
__device__ __half g_WqkvT[3072 * 1024];       // W_qkv^T fp16 [N,K]
__device__ __half g_WoutT[1024 * 1024];       // W_out^T fp16 [N,K]

// ---------------- helpers ----------------
__device__ __forceinline__ uint32_t smem_u32(const void* p) {
    uint32_t a;
    asm("{ .reg .u64 t; cvta.to.shared.u64 t, %1; cvt.u32.u64 %0, t; }" : "=r"(a) : "l"(p));
    return a;
}
__device__ __forceinline__ void cp_async16(uint32_t dst, const void* src) {
    asm volatile("cp.async.cg.shared.global [%0], [%1], 16;" :: "r"(dst), "l"(src));
}
#define CP_COMMIT()  asm volatile("cp.async.commit_group;" ::: "memory")
#define CP_WAIT(n)   asm volatile("cp.async.wait_group %0;" :: "n"(n) : "memory")

__device__ __forceinline__ void mma_f16(float* d, const unsigned* a, const unsigned* b) {
    asm volatile(
        "mma.sync.aligned.m16n8k16.row.col.f32.f16.f16.f32 "
        "{%0,%1,%2,%3}, {%4,%5,%6,%7}, {%8,%9}, {%0,%1,%2,%3};"
        : "+f"(d[0]), "+f"(d[1]), "+f"(d[2]), "+f"(d[3])
        : "r"(a[0]), "r"(a[1]), "r"(a[2]), "r"(a[3]), "r"(b[0]), "r"(b[1]));
}
__device__ __forceinline__ unsigned packh2(float lo, float hi) {
    __half2 h = __floats2half2_rn(lo, hi);
    return *reinterpret_cast<unsigned*>(&h);
}

// ---------------- prep kernels ----------------
__global__ void f2h_kernel(const float4* __restrict__ in, uint2* __restrict__ out) {
    int i = blockIdx.x * blockDim.x + threadIdx.x;
    float4 v = in[i];
    out[i] = make_uint2(packh2(v.x, v.y), packh2(v.z, v.w));
}
__global__ void transpose_h(const float* __restrict__ W, __half* __restrict__ Wt, int K, int N) {
    __shared__ float t[32][33];
    int n0 = blockIdx.x * 32, k0 = blockIdx.y * 32;
    int tx = threadIdx.x, ty = threadIdx.y;
#pragma unroll
    for (int j = 0; j < 32; j += 8)
        t[ty + j][tx] = W[(size_t)(k0 + ty + j) * N + n0 + tx];
    __syncthreads();
#pragma unroll
    for (int j = 0; j < 32; j += 8)
        Wt[(size_t)(n0 + ty + j) * K + k0 + tx] = __float2half(t[tx][ty + j]);
}

// ---------------- fp16 mma GEMM, BK=32, 3-stage ring ----------------
// C[M,N] = A[M,1024] @ Bt[N,1024]^T + bias. 128x128 tile, 256 threads,
// warps 2x4, warp tile 64x32. Rows: 16 data words + 4 pad (stride 20 words).
#define GK 1024
#define NSTEPS 32
#define AS_W (128 * 20)
#define BS_W (128 * 20)
#define STAGE_W (AS_W + BS_W)       // 5120 words
#define STAGE_BYTES (STAGE_W * 4)   // 20480
#define GEMM_SMEM (3 * STAGE_BYTES) // 61440

template <bool SPLIT>
__global__ __launch_bounds__(256, 2)
void hgemm(const __half* __restrict__ A, const __half* __restrict__ Bt,
           const float* __restrict__ bias, float* __restrict__ C, int N)
{
    extern __shared__ unsigned smw[];
    const uint32_t sbase = smem_u32(smw);

    const int tid  = threadIdx.x;
    const int lane = tid & 31;
    const int warp = tid >> 5;
    const int gid  = lane >> 2, tg = lane & 3;
    const int wm   = warp >> 2, wn = warp & 3;
    const int rowBase = blockIdx.y * 128;
    const int colBase = blockIdx.x * 128;

    float acc[4][4][4];
#pragma unroll
    for (int mt = 0; mt < 4; mt++)
#pragma unroll
        for (int nt = 0; nt < 4; nt++)
#pragma unroll
            for (int r = 0; r < 4; r++) acc[mt][nt][r] = 0.0f;

    auto fill = [&](int s, int k0) {
        uint32_t sA = sbase + s * STAGE_BYTES;
        uint32_t sB = sA + AS_W * 4;
        // 128 rows x 4 chunks (32 halves = 64B per row slice)
#pragma unroll
        for (int i = 0; i < 2; i++) {
            int f = tid + (i << 8);
            int r = f >> 2, c = f & 3;
            cp_async16(sA + r * 80 + c * 16, A + (size_t)(rowBase + r) * GK + k0 + c * 8);
        }
#pragma unroll
        for (int i = 0; i < 2; i++) {
            int f = tid + (i << 8);
            int r = f >> 2, c = f & 3;
            cp_async16(sB + r * 80 + c * 16, Bt + (size_t)(colBase + r) * GK + k0 + c * 8);
        }
        CP_COMMIT();
    };

    auto compute = [&](int s) {
        const unsigned* As = smw + s * STAGE_W;
        const unsigned* Bs = As + AS_W;
#pragma unroll
        for (int ks = 0; ks < 2; ks++) {
            unsigned af[4][4];
#pragma unroll
            for (int mt = 0; mt < 4; mt++) {
                int r0 = (wm * 64 + mt * 16 + gid) * 20 + ks * 8 + tg;
                af[mt][0] = As[r0];
                af[mt][1] = As[r0 + 160];   // +8 rows
                af[mt][2] = As[r0 + 4];     // k +8
                af[mt][3] = As[r0 + 164];
            }
            unsigned bf[4][2];
#pragma unroll
            for (int nt = 0; nt < 4; nt++) {
                int c0 = (wn * 32 + nt * 8 + gid) * 20 + ks * 8 + tg;
                bf[nt][0] = Bs[c0];
                bf[nt][1] = Bs[c0 + 4];
            }
#pragma unroll
            for (int mt = 0; mt < 4; mt++)
#pragma unroll
                for (int nt = 0; nt < 4; nt++)
                    mma_f16(acc[mt][nt], af[mt], bf[nt]);
        }
    };

    fill(0, 0);
    fill(1, 32);

    int s = 0, sf = 2;
#pragma unroll 1
    for (int i = 0; i < NSTEPS; i++) {
        if (i == NSTEPS - 1) { CP_WAIT(0); } else { CP_WAIT(1); }
        __syncthreads();
        if (i + 2 < NSTEPS) {
            fill(sf, (i + 2) * 32);
            sf = (sf == 2) ? 0 : sf + 1;
        }
        compute(s);
        s = (s == 2) ? 0 : s + 1;
    }

    // Epilogue
#pragma unroll
    for (int mt = 0; mt < 4; mt++) {
        int m = rowBase + wm * 64 + mt * 16 + gid;
#pragma unroll
        for (int nt = 0; nt < 4; nt++) {
            int n = colBase + wn * 32 + nt * 8 + 2 * tg;
            float2 bv = *(const float2*)(bias + n);
            float2 v0 = make_float2(acc[mt][nt][0] + bv.x, acc[mt][nt][1] + bv.y);
            float2 v1 = make_float2(acc[mt][nt][2] + bv.x, acc[mt][nt][3] + bv.y);
            if (SPLIT) {
                const int part = n >> 10, dcol = n & 1023;
                const int hh = dcol >> 6, hd = dcol & 63;
                const int bb = m >> 11, si = m & 2047;
                const int si1 = (m + 8) & 2047;    // same bb (128-row tile within batch)
                if (part == 0) {  // Q: pre-scale into exp2 domain
                    v0.x *= SCALE_LOG2E; v0.y *= SCALE_LOG2E;
                    v1.x *= SCALE_LOG2E; v1.y *= SCALE_LOG2E;
                }
                if (part < 2) {
                    __half* dst = (part == 0) ? g_Q : g_K;
                    size_t base = (((size_t)bb * 16 + hh) * 2048);
                    *(__half2*)(dst + (base + si)  * 64 + hd) = __floats2half2_rn(v0.x, v0.y);
                    *(__half2*)(dst + (base + si1) * 64 + hd) = __floats2half2_rn(v1.x, v1.y);
                } else {          // V transposed: [bh][hd][s]
                    size_t base = ((size_t)bb * 16 + hh) * 64;
                    g_Vt[(base + hd)     * 2048 + si]  = __float2half(v0.x);
                    g_Vt[(base + hd + 1) * 2048 + si]  = __float2half(v0.y);
                    g_Vt[(base + hd)     * 2048 + si1] = __float2half(v1.x);
                    g_Vt[(base + hd + 1) * 2048 + si1] = __float2half(v1.y);
                }
            } else {
                *(float2*)(C + (size_t)m * N + n) = v0;
                *(float2*)(C + (size_t)(m + 8) * N + n) = v1;
            }
        }
    }
}

// ---------------- causal flash attention, fp16 ----------------
// BM=128, BN=64, 256 threads, 2 CTAs/SM. Rows = 32 data words + 4 pad (36).
// Q: 128 rows x 8 chunks; K/Vt: 64 rows x 8 chunks (full 128B rows!).
#define Q_W (128 * 36)
#define K_W (64 * 36)
#define V_W (64 * 36)
#define KV_STAGE_W (K_W + V_W)
#define FLASH_SMEM_BYTES ((Q_W + 2 * KV_STAGE_W) * 4)   // 55296

__global__ __launch_bounds__(256, 2)
void flash_h(__half* __restrict__ Out)
{
    extern __shared__ unsigned sm[];
    const uint32_t sbase = smem_u32(sm);

    const int qb = (gridDim.x - 1) - blockIdx.x;   // big tiles first
    const int bh = blockIdx.y;
    const int b = bh >> 4, h = bh & 15;
    const int tid = threadIdx.x, lane = tid & 31, w = tid >> 5;
    const int gid = lane >> 2, tg = lane & 3;

    const __half* Qg  = g_Q  + ((size_t)bh * 2048 + qb * 128) * 64;
    const __half* Kg  = g_K  + (size_t)bh * 2048 * 64;
    const __half* Vtg = g_Vt + (size_t)bh * 64 * 2048;

    auto fill_kv = [&](int s, int kt) {
        uint32_t kb = sbase + (Q_W + s * KV_STAGE_W) * 4;
        uint32_t vb = kb + K_W * 4;
        // K: 64 rows x 8 chunks (64 halves = 128B per row)
#pragma unroll
        for (int i = 0; i < 2; i++) {
            int f = tid + (i << 8);
            int r = f >> 3, c = f & 7;
            cp_async16(kb + r * 144 + c * 16, Kg + ((size_t)kt * 64 + r) * 64 + c * 8);
        }
        // Vt: 64 d-rows x 8 chunks of keys
#pragma unroll
        for (int i = 0; i < 2; i++) {
            int f = tid + (i << 8);
            int r = f >> 3, c = f & 7;
            cp_async16(vb + r * 144 + c * 16, Vtg + (size_t)r * 2048 + kt * 64 + c * 8);
        }
        CP_COMMIT();
    };

    // Q fill: 128 rows x 8 chunks (raw copy; already scaled + fp16)
#pragma unroll
    for (int i = 0; i < 4; i++) {
        int f = tid + (i << 8);
        int r = f >> 3, c = f & 7;
        cp_async16(sbase + r * 144 + c * 16, Qg + (size_t)r * 64 + c * 8);
    }
    CP_COMMIT();
    fill_kv(0, 0);

    float m0 = -1e30f, m1 = -1e30f, l0 = 0.0f, l1 = 0.0f;
    float o[8][4];
#pragma unroll
    for (int nt = 0; nt < 8; nt++)
#pragma unroll
        for (int r = 0; r < 4; r++) o[nt][r] = 0.0f;

    const unsigned* Qs = sm;
    const int ktmax = 2 * qb + 1;

    for (int kt = 0; kt <= ktmax; kt++) {
        CP_WAIT(0);
        __syncthreads();
        if (kt < ktmax) fill_kv((kt + 1) & 1, kt + 1);

        const unsigned* Ksp = sm + Q_W + (kt & 1) * KV_STAGE_W;
        const unsigned* Vsp = Ksp + K_W;

        // S = Q @ K^T   (4 k-chunks of 16 over d=64)
        float sacc[8][4];
#pragma unroll
        for (int nt = 0; nt < 8; nt++)
#pragma unroll
            for (int r = 0; r < 4; r++) sacc[nt][r] = 0.0f;

#pragma unroll
        for (int ks = 0; ks < 4; ks++) {
            unsigned af[4];
            int q0 = (w * 16 + gid) * 36 + ks * 8 + tg;
            af[0] = Qs[q0];
            af[1] = Qs[q0 + 288];    // +8 rows
            af[2] = Qs[q0 + 4];      // k +8
            af[3] = Qs[q0 + 292];
#pragma unroll
            for (int nt = 0; nt < 8; nt++) {
                unsigned bf[2];
                int c0 = (nt * 8 + gid) * 36 + ks * 8 + tg;
                bf[0] = Ksp[c0];
                bf[1] = Ksp[c0 + 4];
                mma_f16(sacc[nt], af, bf);
            }
        }

        if (kt >= 2 * qb) {
            int r0 = qb * 128 + w * 16 + gid;
            int r1 = r0 + 8;
#pragma unroll
            for (int nt = 0; nt < 8; nt++) {
                int c = kt * 64 + nt * 8 + 2 * tg;
                if (c > r0)     sacc[nt][0] = -1e30f;
                if (c + 1 > r0) sacc[nt][1] = -1e30f;
                if (c > r1)     sacc[nt][2] = -1e30f;
                if (c + 1 > r1) sacc[nt][3] = -1e30f;
            }
        }

        // online softmax (exp2 domain), quad reductions
        float mx0 = -1e30f, mx1 = -1e30f;
#pragma unroll
        for (int nt = 0; nt < 8; nt++) {
            mx0 = fmaxf(mx0, fmaxf(sacc[nt][0], sacc[nt][1]));
            mx1 = fmaxf(mx1, fmaxf(sacc[nt][2], sacc[nt][3]));
        }
        mx0 = fmaxf(mx0, __shfl_xor_sync(0xffffffffu, mx0, 1));
        mx0 = fmaxf(mx0, __shfl_xor_sync(0xffffffffu, mx0, 2));
        mx1 = fmaxf(mx1, __shfl_xor_sync(0xffffffffu, mx1, 1));
        mx1 = fmaxf(mx1, __shfl_xor_sync(0xffffffffu, mx1, 2));
        float mn0 = fmaxf(m0, mx0), mn1 = fmaxf(m1, mx1);
        float a0 = exp2f(m0 - mn0), a1 = exp2f(m1 - mn1);
        m0 = mn0; m1 = mn1;
        float rs0 = 0.0f, rs1 = 0.0f;
#pragma unroll
        for (int nt = 0; nt < 8; nt++) {
            sacc[nt][0] = exp2f(sacc[nt][0] - mn0); rs0 += sacc[nt][0];
            sacc[nt][1] = exp2f(sacc[nt][1] - mn0); rs0 += sacc[nt][1];
            sacc[nt][2] = exp2f(sacc[nt][2] - mn1); rs1 += sacc[nt][2];
            sacc[nt][3] = exp2f(sacc[nt][3] - mn1); rs1 += sacc[nt][3];
        }
        rs0 += __shfl_xor_sync(0xffffffffu, rs0, 1);
        rs0 += __shfl_xor_sync(0xffffffffu, rs0, 2);
        rs1 += __shfl_xor_sync(0xffffffffu, rs1, 1);
        rs1 += __shfl_xor_sync(0xffffffffu, rs1, 2);
        l0 = l0 * a0 + rs0;
        l1 = l1 * a1 + rs1;
#pragma unroll
        for (int nt = 0; nt < 8; nt++) {
            o[nt][0] *= a0; o[nt][1] *= a0; o[nt][2] *= a1; o[nt][3] *= a1;
        }

        // O += P @ V : A-frag of P taken directly from the QK C-frag.
#pragma unroll
        for (int ks = 0; ks < 4; ks++) {
            unsigned af[4];
            af[0] = packh2(sacc[2 * ks][0],     sacc[2 * ks][1]);      // row gid,   k=16ks+2tg
            af[1] = packh2(sacc[2 * ks][2],     sacc[2 * ks][3]);      // row gid+8
            af[2] = packh2(sacc[2 * ks + 1][0], sacc[2 * ks + 1][1]);  // k +8
            af[3] = packh2(sacc[2 * ks + 1][2], sacc[2 * ks + 1][3]);
#pragma unroll
            for (int nt = 0; nt < 8; nt++) {
                unsigned bf[2];
                int c0 = (nt * 8 + gid) * 36 + ks * 8 + tg;
                bf[0] = Vsp[c0];
                bf[1] = Vsp[c0 + 4];
                mma_f16(o[nt], af, bf);
            }
        }
    }

    // Normalize, write merged [B,S,D] as fp16
    float i0 = 1.0f / l0, i1 = 1.0f / l1;
    int r0 = qb * 128 + w * 16 + gid;
    __half* p0 = Out + ((size_t)b * 2048 + r0) * 1024 + h * 64;
    __half* p1 = p0 + (size_t)8 * 1024;
#pragma unroll
    for (int nt = 0; nt < 8; nt++) {
        *(__half2*)(p0 + nt * 8 + 2 * tg) = __floats2half2_rn(o[nt][0] * i0, o[nt][1] * i0);
        *(__half2*)(p1 + nt * 8 + 2 * tg) = __floats2half2_rn(o[nt][2] * i1, o[nt][3] * i1);
    }
}

// ---------------------------------------------------------------------------
extern "C" void kernel_launch(void* const* d_in, const int* in_sizes, int n_in,
                              void* d_out, int out_size)
{
    const float* x     = (const float*)d_in[0];
    const float* W_qkv = (const float*)d_in[1];
    const float* b_qkv = (const float*)d_in[2];
    const float* W_out = (const float*)d_in[3];
    const float* b_out = (const float*)d_in[4];
    float* out = (float*)d_out;

    __half *attn, *xh, *wqkvT, *woutT;
    cudaGetSymbolAddress((void**)&attn,  g_attn);
    cudaGetSymbolAddress((void**)&xh,    g_xh);
    cudaGetSymbolAddress((void**)&wqkvT, g_WqkvT);
    cudaGetSymbolAddress((void**)&woutT, g_WoutT);

    // prep: fp16 conversions (+ weight transposes to [N,K])
    f2h_kernel<<<8192, 256>>>((const float4*)x, (uint2*)xh);
    transpose_h<<<dim3(96, 32), dim3(32, 8)>>>(W_qkv, wqkvT, 1024, 3072);
    transpose_h<<<dim3(32, 32), dim3(32, 8)>>>(W_out, woutT, 1024, 1024);

    cudaFuncSetAttribute(hgemm<true>,  cudaFuncAttributeMaxDynamicSharedMemorySize, GEMM_SMEM);
    cudaFuncSetAttribute(hgemm<false>, cudaFuncAttributeMaxDynamicSharedMemorySize, GEMM_SMEM);

    // 1) QKV projection (bias + head-split + Q-scale + V-transpose in epilogue)
    hgemm<true><<<dim3(24, 64), 256, GEMM_SMEM>>>(xh, wqkvT, b_qkv, nullptr, 3072);

    // 2) causal flash attention
    cudaFuncSetAttribute(flash_h, cudaFuncAttributeMaxDynamicSharedMemorySize, FLASH_SMEM_BYTES);
    flash_h<<<dim3(16, 64), 256, FLASH_SMEM_BYTES>>>(attn);

    // 3) output projection (fp32 out)
    hgemm<false><<<dim3(8, 64), 256, GEMM_SMEM>>>(attn, woutT, b_out, out, 1024);
}